// round 4
// baseline (speedup 1.0000x reference)
#include <cuda_runtime.h>
#include <cuda_bf16.h>
#include <math.h>
#include <stdint.h>

// ---------------- problem constants ----------------
#define Bsz 64
#define Hd  256
#define Dd  768
#define NRn 100000
#define ERn 400000
#define NCn 100000
#define ECn 300000
#define Gn  512

// ---------------- device scratch ----------------
__device__ float g_XWr[(size_t)NRn * Hd];
__device__ float g_P1r[(size_t)NRn * Hd];
__device__ float g_XWc[(size_t)NCn * Hd];
__device__ float g_P1c[(size_t)NCn * Hd];
__device__ float g_dinv_r[NRn];
__device__ float g_dinv_c[NCn];
__device__ float g_Wf_r[Dd * Hd];
__device__ float g_Wf_c[Dd * Hd];
__device__ __nv_bfloat16 g_WtHiR[Hd * Dd];
__device__ __nv_bfloat16 g_WtLoR[Hd * Dd];
__device__ __nv_bfloat16 g_WtHiC[Hd * Dd];
__device__ __nv_bfloat16 g_WtLoC[Hd * Dd];
__device__ float g_pooled_r[Bsz * Hd];
__device__ float g_pooledG[Gn * Hd];
__device__ float g_graphs[Gn * Hd];
__device__ float g_reps[Bsz * 5 * Hd];
__device__ float g_hmid[Bsz * Hd];
// CSR scratch
__device__ int g_cnt_r[NRn];
__device__ int g_cnt_c[NCn];
__device__ int g_rowoff_r[NRn + 1];
__device__ int g_rowoff_c[NCn + 1];
__device__ int g_esrc_r[ERn];
__device__ int g_esrc_c[ECn];
__device__ int g_bsum[512];

// ---------------- small utility kernels ----------------
__global__ void filli_kernel(int* p, int n, int v) {
    int i = blockIdx.x * blockDim.x + threadIdx.x;
    if (i < n) p[i] = v;
}

__global__ void count_kernel(const int* __restrict__ dst, int* __restrict__ cnt, int E) {
    int e = blockIdx.x * blockDim.x + threadIdx.x;
    if (e < E) atomicAdd(&cnt[dst[e]], 1);
}

__global__ void dinv_kernel(const int* __restrict__ cnt, float* __restrict__ dinv, int n) {
    int i = blockIdx.x * blockDim.x + threadIdx.x;
    if (i < n) dinv[i] = rsqrtf((float)(cnt[i] + 1));
}

// ---------------- multi-block exclusive scan ----------------
__global__ void scan_blocksum_kernel(const int* __restrict__ cnt, int* __restrict__ bsum, int n) {
    __shared__ int sh[256];
    int tid = threadIdx.x;
    int i = blockIdx.x * 256 + tid;
    sh[tid] = (i < n) ? cnt[i] : 0;
    __syncthreads();
    for (int off = 128; off > 0; off >>= 1) {
        if (tid < off) sh[tid] += sh[tid + off];
        __syncthreads();
    }
    if (tid == 0) bsum[blockIdx.x] = sh[0];
}

__global__ void scan_bsum_kernel(int* __restrict__ bsum, int* __restrict__ rowoff, int nb, int n) {
    __shared__ int sh[512];
    int tid = threadIdx.x;  // 512
    int v = (tid < nb) ? bsum[tid] : 0;
    sh[tid] = v;
    __syncthreads();
    for (int off = 1; off < 512; off <<= 1) {
        int t = (tid >= off) ? sh[tid - off] : 0;
        __syncthreads();
        sh[tid] += t;
        __syncthreads();
    }
    if (tid < nb) bsum[tid] = sh[tid] - v;   // exclusive
    if (tid == 511) rowoff[n] = sh[511];     // total
}

__global__ void scan_final_kernel(const int* __restrict__ cnt, const int* __restrict__ bsum,
                                  int* __restrict__ rowoff, int n) {
    __shared__ int sh[256];
    int tid = threadIdx.x;
    int i = blockIdx.x * 256 + tid;
    int v = (i < n) ? cnt[i] : 0;
    sh[tid] = v;
    __syncthreads();
    for (int off = 1; off < 256; off <<= 1) {
        int t = (tid >= off) ? sh[tid - off] : 0;
        __syncthreads();
        sh[tid] += t;
        __syncthreads();
    }
    if (i < n) rowoff[i] = bsum[blockIdx.x] + sh[tid] - v;
}

__global__ void scatter_kernel(const int* __restrict__ src, const int* __restrict__ dst,
                               const int* __restrict__ rowoff, int* __restrict__ cursor,
                               int* __restrict__ esrc, int E) {
    int e = blockIdx.x * blockDim.x + threadIdx.x;
    if (e < E) {
        int d = dst[e];
        int pos = rowoff[d] + atomicAdd(&cursor[d], 1);
        esrc[pos] = src[e];
    }
}

// ---------------- vectorized CSR gather propagation (4 nodes/block, float4) ----------------
__device__ __forceinline__ float4 relu4(float4 v) {
    return make_float4(fmaxf(v.x, 0.f), fmaxf(v.y, 0.f), fmaxf(v.z, 0.f), fmaxf(v.w, 0.f));
}

template <int DORELU>
__global__ __launch_bounds__(256) void gather_prop_v4_kernel(
    const float* __restrict__ in, float* __restrict__ out,
    const int* __restrict__ rowoff, const int* __restrict__ esrc,
    const float* __restrict__ dinv, int N)
{
    int local = threadIdx.x >> 6;           // node within block (0..3)
    int l64 = threadIdx.x & 63;             // lane within node
    int n = blockIdx.x * 4 + local;
    if (n >= N) return;
    int j4 = l64 * 4;
    int beg = __ldg(&rowoff[n]), end = __ldg(&rowoff[n + 1]);
    float di = __ldg(&dinv[n]);
    float4 v = *(const float4*)&in[(size_t)n * Hd + j4];
    if (DORELU) v = relu4(v);
    float ax = v.x * di, ay = v.y * di, az = v.z * di, aw = v.w * di;
    int e = beg;
    for (; e + 2 <= end; e += 2) {
        int s0 = __ldg(&esrc[e]);
        int s1 = __ldg(&esrc[e + 1]);
        float w0 = __ldg(&dinv[s0]);
        float w1 = __ldg(&dinv[s1]);
        float4 x0 = *(const float4*)&in[(size_t)s0 * Hd + j4];
        float4 x1 = *(const float4*)&in[(size_t)s1 * Hd + j4];
        if (DORELU) { x0 = relu4(x0); x1 = relu4(x1); }
        ax += x0.x * w0 + x1.x * w1;
        ay += x0.y * w0 + x1.y * w1;
        az += x0.z * w0 + x1.z * w1;
        aw += x0.w * w0 + x1.w * w1;
    }
    if (e < end) {
        int s0 = __ldg(&esrc[e]);
        float w0 = __ldg(&dinv[s0]);
        float4 x0 = *(const float4*)&in[(size_t)s0 * Hd + j4];
        if (DORELU) x0 = relu4(x0);
        ax += x0.x * w0; ay += x0.y * w0; az += x0.z * w0; aw += x0.w * w0;
    }
    *(float4*)&out[(size_t)n * Hd + j4] = make_float4(ax * di, ay * di, az * di, aw * di);
}

// layer-2 gather fused with segment-sum pooling (input pre-relu'd inside)
__global__ __launch_bounds__(256) void gather_prop_pool_v4_kernel(
    const float* __restrict__ in,
    const int* __restrict__ rowoff, const int* __restrict__ esrc,
    const float* __restrict__ dinv, const int* __restrict__ batch,
    float* __restrict__ pool, int N)
{
    int local = threadIdx.x >> 6;
    int l64 = threadIdx.x & 63;
    int n = blockIdx.x * 4 + local;
    if (n >= N) return;
    int j4 = l64 * 4;
    int beg = __ldg(&rowoff[n]), end = __ldg(&rowoff[n + 1]);
    float di = __ldg(&dinv[n]);
    float4 v = relu4(*(const float4*)&in[(size_t)n * Hd + j4]);
    float ax = v.x * di, ay = v.y * di, az = v.z * di, aw = v.w * di;
    int e = beg;
    for (; e + 2 <= end; e += 2) {
        int s0 = __ldg(&esrc[e]);
        int s1 = __ldg(&esrc[e + 1]);
        float w0 = __ldg(&dinv[s0]);
        float w1 = __ldg(&dinv[s1]);
        float4 x0 = relu4(*(const float4*)&in[(size_t)s0 * Hd + j4]);
        float4 x1 = relu4(*(const float4*)&in[(size_t)s1 * Hd + j4]);
        ax += x0.x * w0 + x1.x * w1;
        ay += x0.y * w0 + x1.y * w1;
        az += x0.z * w0 + x1.z * w1;
        aw += x0.w * w0 + x1.w * w1;
    }
    if (e < end) {
        int s0 = __ldg(&esrc[e]);
        float w0 = __ldg(&dinv[s0]);
        float4 x0 = relu4(*(const float4*)&in[(size_t)s0 * Hd + j4]);
        ax += x0.x * w0; ay += x0.y * w0; az += x0.z * w0; aw += x0.w * w0;
    }
    int b = __ldg(&batch[n]);
    float* p = &pool[(size_t)b * Hd + j4];
    atomicAdd(p + 0, ax * di);
    atomicAdd(p + 1, ay * di);
    atomicAdd(p + 2, az * di);
    atomicAdd(p + 3, aw * di);
}

__device__ __forceinline__ int lower_bound_dev(const int* a, int n, int v) {
    int lo = 0, hi = n;
    while (lo < hi) { int mid = (lo + hi) >> 1; if (a[mid] < v) lo = mid + 1; else hi = mid; }
    return lo;
}

__global__ void pool_partial_kernel(const float* __restrict__ x, const int* __restrict__ seg,
                                    int n, float* __restrict__ acc, int chunks) {
    int b = blockIdx.x;
    int chunk = blockIdx.y;
    int start = lower_bound_dev(seg, n, b);
    int end   = lower_bound_dev(seg, n, b + 1);
    int len = end - start;
    if (len <= 0) return;
    int per = (len + chunks - 1) / chunks;
    int s0 = start + chunk * per;
    int s1 = s0 + per; if (s1 > end) s1 = end;
    if (s0 >= s1) return;
    int j = threadIdx.x;
    float a = 0.0f;
    for (int r = s0; r < s1; r++) a += x[(size_t)r * Hd + j];
    atomicAdd(&acc[b * Hd + j], a);
}

__global__ void pool_div_kernel(const float* __restrict__ acc, const int* __restrict__ seg,
                                int n, float* __restrict__ dst, int ld) {
    int b = blockIdx.x;
    int j = threadIdx.x;
    int cnt = lower_bound_dev(seg, n, b + 1) - lower_bound_dev(seg, n, b);
    float c = fmaxf((float)cnt, 1.0f);
    dst[(size_t)b * ld + j] = acc[b * Hd + j] / c;
}

// ---------------- transpose + bf16 split of fused weight ----------------
__global__ void convtrans_kernel(const float* __restrict__ W,
                                 __nv_bfloat16* __restrict__ oHi,
                                 __nv_bfloat16* __restrict__ oLo) {
    int i = blockIdx.x * blockDim.x + threadIdx.x;
    if (i >= Dd * Hd) return;
    int k = i / Hd, n = i % Hd;
    float f = W[i];
    __nv_bfloat16 h = __float2bfloat16(f);
    float r = f - __bfloat162float(h);
    oHi[(size_t)n * Dd + k] = h;
    oLo[(size_t)n * Dd + k] = __float2bfloat16(r);
}

// ---------------- tensor-core GEMM (bf16 split, 3 products) ----------------
__device__ __forceinline__ void ldsm_x4(uint32_t r[4], const void* p) {
    uint32_t a = (uint32_t)__cvta_generic_to_shared(p);
    asm volatile("ldmatrix.sync.aligned.m8n8.x4.shared.b16 {%0,%1,%2,%3}, [%4];"
                 : "=r"(r[0]), "=r"(r[1]), "=r"(r[2]), "=r"(r[3]) : "r"(a));
}

__device__ __forceinline__ void mma_bf16(float acc[4], uint32_t a0, uint32_t a1,
                                         uint32_t a2, uint32_t a3,
                                         uint32_t b0, uint32_t b1) {
    asm volatile(
        "mma.sync.aligned.m16n8k16.row.col.f32.bf16.bf16.f32 "
        "{%0,%1,%2,%3},{%4,%5,%6,%7},{%8,%9},{%0,%1,%2,%3};"
        : "+f"(acc[0]), "+f"(acc[1]), "+f"(acc[2]), "+f"(acc[3])
        : "r"(a0), "r"(a1), "r"(a2), "r"(a3), "r"(b0), "r"(b1));
}

__global__ __launch_bounds__(256) void gemm_tc_kernel(
    const float* __restrict__ A,
    const __nv_bfloat16* __restrict__ BtHi,
    const __nv_bfloat16* __restrict__ BtLo,
    float* __restrict__ C, int M)
{
    const int K = Dd;
    const int LDS_STRIDE = 40;
    __shared__ __nv_bfloat16 AsH[128][LDS_STRIDE];
    __shared__ __nv_bfloat16 AsL[128][LDS_STRIDE];
    __shared__ __nv_bfloat16 BsH[128][LDS_STRIDE];
    __shared__ __nv_bfloat16 BsL[128][LDS_STRIDE];

    int tid = threadIdx.x;
    int warp = tid >> 5, lane = tid & 31;
    int bRow = blockIdx.y * 128, bCol = blockIdx.x * 128;
    int wm = (warp >> 2) * 64;
    int wn = (warp & 3) * 32;

    float acc[4][4][4];
#pragma unroll
    for (int a = 0; a < 4; a++)
#pragma unroll
        for (int b = 0; b < 4; b++)
#pragma unroll
            for (int c = 0; c < 4; c++) acc[a][b][c] = 0.0f;

    float4 aR[4];
    const float4 z4 = make_float4(0.f, 0.f, 0.f, 0.f);
#define LOAD_A(k0)                                                            \
    {                                                                         \
        _Pragma("unroll")                                                     \
        for (int l = 0; l < 4; l++) {                                         \
            int i = tid + l * 256;                                            \
            int r = i >> 3, c4 = (i & 7) * 4;                                 \
            int gr = bRow + r;                                                \
            aR[l] = (gr < M) ? *(const float4*)&A[(size_t)gr * K + (k0) + c4] \
                             : z4;                                            \
        }                                                                     \
    }

    LOAD_A(0);

    for (int it = 0; it < K / 32; it++) {
        int k0 = it * 32;
#pragma unroll
        for (int l = 0; l < 2; l++) {
            int i = tid + l * 256;
            int r = i >> 2, c8 = (i & 3) * 8;
            *(float4*)&BsH[r][c8] = *(const float4*)&BtHi[(size_t)(bCol + r) * K + k0 + c8];
            *(float4*)&BsL[r][c8] = *(const float4*)&BtLo[(size_t)(bCol + r) * K + k0 + c8];
        }
#pragma unroll
        for (int l = 0; l < 4; l++) {
            int i = tid + l * 256;
            int r = i >> 3, c4 = (i & 7) * 4;
            float f[4] = {aR[l].x, aR[l].y, aR[l].z, aR[l].w};
            __nv_bfloat16 h[4], lo[4];
#pragma unroll
            for (int j = 0; j < 4; j++) {
                h[j] = __float2bfloat16(f[j]);
                lo[j] = __float2bfloat16(f[j] - __bfloat162float(h[j]));
            }
            *(__nv_bfloat162*)&AsH[r][c4]     = __nv_bfloat162(h[0], h[1]);
            *(__nv_bfloat162*)&AsH[r][c4 + 2] = __nv_bfloat162(h[2], h[3]);
            *(__nv_bfloat162*)&AsL[r][c4]     = __nv_bfloat162(lo[0], lo[1]);
            *(__nv_bfloat162*)&AsL[r][c4 + 2] = __nv_bfloat162(lo[2], lo[3]);
        }
        __syncthreads();

        if (it < K / 32 - 1) LOAD_A(k0 + 32);

        int mt = lane >> 3, ri = lane & 7;
#pragma unroll
        for (int ks = 0; ks < 2; ks++) {
            int colOff = ks * 16 + (mt >> 1) * 8;
            uint32_t aH[4][4], aL[4][4], bH[2][4], bL[2][4];
#pragma unroll
            for (int mi = 0; mi < 4; mi++) {
                int row = wm + mi * 16 + (mt & 1) * 8 + ri;
                ldsm_x4(aH[mi], &AsH[row][colOff]);
                ldsm_x4(aL[mi], &AsL[row][colOff]);
            }
#pragma unroll
            for (int bj = 0; bj < 2; bj++) {
                int row = wn + bj * 16 + (mt & 1) * 8 + ri;
                ldsm_x4(bH[bj], &BsH[row][colOff]);
                ldsm_x4(bL[bj], &BsL[row][colOff]);
            }
#pragma unroll
            for (int mi = 0; mi < 4; mi++)
#pragma unroll
                for (int nj = 0; nj < 4; nj++) {
                    int bj = nj >> 1, s = nj & 1;
                    mma_bf16(acc[mi][nj], aH[mi][0], aH[mi][1], aH[mi][2], aH[mi][3],
                             bH[bj][s], bH[bj][s + 2]);
                    mma_bf16(acc[mi][nj], aH[mi][0], aH[mi][1], aH[mi][2], aH[mi][3],
                             bL[bj][s], bL[bj][s + 2]);
                    mma_bf16(acc[mi][nj], aL[mi][0], aL[mi][1], aL[mi][2], aL[mi][3],
                             bH[bj][s], bH[bj][s + 2]);
                }
        }
        __syncthreads();
    }

    int g = lane >> 2, t = lane & 3;
#pragma unroll
    for (int mi = 0; mi < 4; mi++)
#pragma unroll
        for (int nj = 0; nj < 4; nj++) {
            int row = bRow + wm + mi * 16 + g;
            int col = bCol + wn + nj * 8 + t * 2;
            if (row < M)
                *(float2*)&C[(size_t)row * Hd + col] = make_float2(acc[mi][nj][0], acc[mi][nj][1]);
            if (row + 8 < M)
                *(float2*)&C[(size_t)(row + 8) * Hd + col] = make_float2(acc[mi][nj][2], acc[mi][nj][3]);
        }
#undef LOAD_A
}

// ---------------- small fp32 GEMM ----------------
__global__ __launch_bounds__(256) void sgemm64_kernel(const float* __restrict__ A, int lda,
                                                      const float* __restrict__ Bm,
                                                      const float* __restrict__ bias,
                                                      float* __restrict__ C, int ldc,
                                                      int M, int N, int K, int doRelu) {
    const int BM = 64, BN = 64, BK = 16, TM = 4, TN = 4;
    __shared__ float As[BK][BM];
    __shared__ float Bs[BK][BN];
    const int tid = threadIdx.x;
    const int bRow = blockIdx.y * BM;
    const int bCol = blockIdx.x * BN;
    const int tx = tid % 16;
    const int ty = tid / 16;

    float acc[TM][TN];
#pragma unroll
    for (int i = 0; i < TM; i++)
#pragma unroll
        for (int j = 0; j < TN; j++) acc[i][j] = 0.0f;

    for (int k0 = 0; k0 < K; k0 += BK) {
        {
            int i = tid;
            int r = i >> 2;
            int c4 = (i & 3) << 2;
            int grow = bRow + r;
            float4 v = make_float4(0.f, 0.f, 0.f, 0.f);
            if (grow < M) v = *reinterpret_cast<const float4*>(&A[(size_t)grow * lda + k0 + c4]);
            As[c4 + 0][r] = v.x; As[c4 + 1][r] = v.y; As[c4 + 2][r] = v.z; As[c4 + 3][r] = v.w;
        }
        {
            int i = tid;
            int r = i >> 4;
            int c = (i & 15) << 2;
            float4 v = *reinterpret_cast<const float4*>(&Bm[(size_t)(k0 + r) * N + bCol + c]);
            *reinterpret_cast<float4*>(&Bs[r][c]) = v;
        }
        __syncthreads();

        float ar[TM], br[TN];
#pragma unroll
        for (int kk = 0; kk < BK; kk++) {
#pragma unroll
            for (int i = 0; i < TM; i++) ar[i] = As[kk][ty * TM + i];
#pragma unroll
            for (int j = 0; j < TN; j++) br[j] = Bs[kk][tx * TN + j];
#pragma unroll
            for (int i = 0; i < TM; i++)
#pragma unroll
                for (int j = 0; j < TN; j++) acc[i][j] += ar[i] * br[j];
        }
        __syncthreads();
    }

#pragma unroll
    for (int i = 0; i < TM; i++) {
        int grow = bRow + ty * TM + i;
        if (grow >= M) continue;
#pragma unroll
        for (int j = 0; j < TN; j++) {
            int gcol = bCol + tx * TN + j;
            float v = acc[i][j];
            if (bias) v += bias[gcol];
            if (doRelu) v = fmaxf(v, 0.0f);
            C[(size_t)grow * ldc + gcol] = v;
        }
    }
}

// ---------------- head ----------------
__global__ void head_kernel(const float* __restrict__ h, const float* __restrict__ W2,
                            const float* __restrict__ b2, const int* __restrict__ label,
                            float* __restrict__ out, int out_size) {
    __shared__ float preds[Bsz][2];
    int tid = threadIdx.x;
    if (tid < Bsz * 2) {
        int r = tid >> 1, c = tid & 1;
        float s = b2[c];
        for (int k = 0; k < Hd; k++) s += h[r * Hd + k] * W2[k * 2 + c];
        preds[r][c] = s;
    }
    __syncthreads();
    if (tid < Bsz * 2 && tid < out_size) out[tid] = preds[tid >> 1][tid & 1];
    if (tid == 0 && out_size >= Bsz * 2 + 1) {
        float loss = 0.0f;
        for (int r = 0; r < Bsz; r++) {
            float a = preds[r][0], b = preds[r][1];
            float m = fmaxf(a, b);
            float lse = m + logf(expf(a - m) + expf(b - m));
            int y = label[r];
            loss += lse - (y ? b : a);
        }
        out[Bsz * 2] = loss / (float)Bsz;
    }
}

// ---------------- launch ----------------
extern "C" void kernel_launch(void* const* d_in, const int* in_sizes, int n_in,
                              void* d_out, int out_size) {
    const float* content  = (const float*)d_in[0];
    const float* video    = (const float*)d_in[1];
    const float* image    = (const float*)d_in[2];
    const float* repost_x = (const float*)d_in[3];
    const float* comment_x= (const float*)d_in[4];
    const float* W_text   = (const float*)d_in[5];
    const float* W_video  = (const float*)d_in[6];
    const float* W_image  = (const float*)d_in[7];
    const float* Wr1      = (const float*)d_in[8];
    const float* Wr2      = (const float*)d_in[9];
    const float* Wc1      = (const float*)d_in[10];
    const float* Wc2      = (const float*)d_in[11];
    const float* W1       = (const float*)d_in[12];
    const float* b1       = (const float*)d_in[13];
    const float* W2       = (const float*)d_in[14];
    const float* b2       = (const float*)d_in[15];
    const int* rei        = (const int*)d_in[16];
    const int* rbatch     = (const int*)d_in[17];
    const int* cei        = (const int*)d_in[18];
    const int* cbatch     = (const int*)d_in[19];
    const int* cgb        = (const int*)d_in[20];
    const int* label      = (const int*)d_in[21];
    float* out            = (float*)d_out;

    float *pXWr, *pP1r, *pXWc, *pP1c, *pDr, *pDc, *pWfr, *pWfc;
    float *pPoolR, *pPoolG, *pGraphs, *pReps, *pHmid;
    __nv_bfloat16 *pWtHiR, *pWtLoR, *pWtHiC, *pWtLoC;
    int *pCntR, *pCntC, *pRoR, *pRoC, *pEsR, *pEsC, *pBsum;
    cudaGetSymbolAddress((void**)&pXWr, g_XWr);
    cudaGetSymbolAddress((void**)&pP1r, g_P1r);
    cudaGetSymbolAddress((void**)&pXWc, g_XWc);
    cudaGetSymbolAddress((void**)&pP1c, g_P1c);
    cudaGetSymbolAddress((void**)&pDr, g_dinv_r);
    cudaGetSymbolAddress((void**)&pDc, g_dinv_c);
    cudaGetSymbolAddress((void**)&pWfr, g_Wf_r);
    cudaGetSymbolAddress((void**)&pWfc, g_Wf_c);
    cudaGetSymbolAddress((void**)&pWtHiR, g_WtHiR);
    cudaGetSymbolAddress((void**)&pWtLoR, g_WtLoR);
    cudaGetSymbolAddress((void**)&pWtHiC, g_WtHiC);
    cudaGetSymbolAddress((void**)&pWtLoC, g_WtLoC);
    cudaGetSymbolAddress((void**)&pPoolR, g_pooled_r);
    cudaGetSymbolAddress((void**)&pPoolG, g_pooledG);
    cudaGetSymbolAddress((void**)&pGraphs, g_graphs);
    cudaGetSymbolAddress((void**)&pReps, g_reps);
    cudaGetSymbolAddress((void**)&pHmid, g_hmid);
    cudaGetSymbolAddress((void**)&pCntR, g_cnt_r);
    cudaGetSymbolAddress((void**)&pCntC, g_cnt_c);
    cudaGetSymbolAddress((void**)&pRoR, g_rowoff_r);
    cudaGetSymbolAddress((void**)&pRoC, g_rowoff_c);
    cudaGetSymbolAddress((void**)&pEsR, g_esrc_r);
    cudaGetSymbolAddress((void**)&pEsC, g_esrc_c);
    cudaGetSymbolAddress((void**)&pBsum, g_bsum);

    const int* r_src = rei;            const int* r_dst = rei + ERn;
    const int* c_src = cei;            const int* c_dst = cei + ECn;

    const int NBr = (NRn + 255) / 256;   // 391
    const int NBc = (NCn + 255) / 256;   // 391

    // ---- fused first-layer weights + bf16 splits (front-loaded) ----
    sgemm64_kernel<<<dim3(Hd / 64, Dd / 64), 256>>>(W_text, Hd, Wr1, nullptr, pWfr, Hd, Dd, Hd, Hd, 0);
    sgemm64_kernel<<<dim3(Hd / 64, Dd / 64), 256>>>(W_text, Hd, Wc1, nullptr, pWfc, Hd, Dd, Hd, Hd, 0);
    convtrans_kernel<<<(Dd * Hd + 255) / 256, 256>>>(pWfr, pWtHiR, pWtLoR);
    convtrans_kernel<<<(Dd * Hd + 255) / 256, 256>>>(pWfc, pWtHiC, pWtLoC);

    // ---- big GEMMs on tensor cores, back-to-back ----
    gemm_tc_kernel<<<dim3(2, (NRn + 127) / 128), 256>>>(repost_x, pWtHiR, pWtLoR, pXWr, NRn);
    gemm_tc_kernel<<<dim3(2, (NCn + 127) / 128), 256>>>(comment_x, pWtHiC, pWtLoC, pXWc, NCn);

    // ---- CSR build: repost (overlaps GEMM tails at wave boundaries) ----
    filli_kernel<<<NBr, 256>>>(pCntR, NRn, 0);
    count_kernel<<<(ERn + 255) / 256, 256>>>(r_dst, pCntR, ERn);
    dinv_kernel<<<NBr, 256>>>(pCntR, pDr, NRn);
    scan_blocksum_kernel<<<NBr, 256>>>(pCntR, pBsum, NRn);
    scan_bsum_kernel<<<1, 512>>>(pBsum, pRoR, NBr, NRn);
    scan_final_kernel<<<NBr, 256>>>(pCntR, pBsum, pRoR, NRn);
    filli_kernel<<<NBr, 256>>>(pCntR, NRn, 0);
    scatter_kernel<<<(ERn + 255) / 256, 256>>>(r_src, r_dst, pRoR, pCntR, pEsR, ERn);

    // ---- CSR build: comment ----
    filli_kernel<<<NBc, 256>>>(pCntC, NCn, 0);
    count_kernel<<<(ECn + 255) / 256, 256>>>(c_dst, pCntC, ECn);
    dinv_kernel<<<NBc, 256>>>(pCntC, pDc, NCn);
    scan_blocksum_kernel<<<NBc, 256>>>(pCntC, pBsum, NCn);
    scan_bsum_kernel<<<1, 512>>>(pBsum, pRoC, NBc, NCn);
    scan_final_kernel<<<NBc, 256>>>(pCntC, pBsum, pRoC, NCn);
    filli_kernel<<<NBc, 256>>>(pCntC, NCn, 0);
    scatter_kernel<<<(ECn + 255) / 256, 256>>>(c_src, c_dst, pRoC, pCntC, pEsC, ECn);

    // ---- repost branch ----
    gather_prop_v4_kernel<0><<<(NRn + 3) / 4, 256>>>(pXWr, pP1r, pRoR, pEsR, pDr, NRn);
    cudaMemsetAsync(pPoolR, 0, (size_t)Bsz * Hd * sizeof(float));
    gather_prop_pool_v4_kernel<<<(NRn + 3) / 4, 256>>>(pP1r, pRoR, pEsR, pDr, rbatch, pPoolR, NRn);
    pool_div_kernel<<<Bsz, Hd>>>(pPoolR, rbatch, NRn, pPoolR, Hd);

    // ---- comment branch ----
    gather_prop_v4_kernel<0><<<(NCn + 3) / 4, 256>>>(pXWc, pP1c, pRoC, pEsC, pDc, NCn);
    cudaMemsetAsync(pPoolG, 0, (size_t)Gn * Hd * sizeof(float));
    gather_prop_pool_v4_kernel<<<(NCn + 3) / 4, 256>>>(pP1c, pRoC, pEsC, pDc, cbatch, pPoolG, NCn);
    pool_div_kernel<<<Gn, Hd>>>(pPoolG, cbatch, NCn, pPoolG, Hd);

    sgemm64_kernel<<<dim3(Hd / 64, Gn / 64), 256>>>(pPoolG, Hd, Wc2, nullptr, pGraphs, Hd, Gn, Hd, Hd, 0);
    cudaMemsetAsync(pHmid, 0, (size_t)Bsz * Hd * sizeof(float));
    pool_partial_kernel<<<dim3(Bsz, 2), Hd>>>(pGraphs, cgb, Gn, pHmid, 2);
    pool_div_kernel<<<Bsz, Hd>>>(pHmid, cgb, Gn, pReps + 2 * Hd, 5 * Hd);

    // ---- assemble reps [64, 1280] ----
    sgemm64_kernel<<<dim3(Hd / 64, 1), 256>>>(content, Dd, W_text, nullptr, pReps + 0 * Hd, 5 * Hd, Bsz, Hd, Dd, 0);
    sgemm64_kernel<<<dim3(Hd / 64, 1), 256>>>(pPoolR, Hd, Wr2, nullptr, pReps + 1 * Hd, 5 * Hd, Bsz, Hd, Hd, 0);
    sgemm64_kernel<<<dim3(Hd / 64, 1), 256>>>(video, Dd, W_video, nullptr, pReps + 3 * Hd, 5 * Hd, Bsz, Hd, Dd, 0);
    sgemm64_kernel<<<dim3(Hd / 64, 1), 256>>>(image, Dd, W_image, nullptr, pReps + 4 * Hd, 5 * Hd, Bsz, Hd, Dd, 0);

    // ---- MLP head ----
    sgemm64_kernel<<<dim3(Hd / 64, 1), 256>>>(pReps, 5 * Hd, W1, b1, pHmid, Hd, Bsz, Hd, 5 * Hd, 1);
    head_kernel<<<1, 128>>>(pHmid, W2, b2, label, out, out_size);
}

// round 5
// speedup vs baseline: 1.1451x; 1.1451x over previous
#include <cuda_runtime.h>
#include <cuda_bf16.h>
#include <math.h>
#include <stdint.h>

// ---------------- problem constants ----------------
#define Bsz 64
#define Hd  256
#define Dd  768
#define NRn 100000
#define ERn 400000
#define NCn 100000
#define ECn 300000
#define Gn  512
#define Hd2 (Hd / 2)

// ---------------- device scratch ----------------
__device__ __nv_bfloat162 g_XWr[(size_t)NRn * Hd2];
__device__ __nv_bfloat162 g_P1r[(size_t)NRn * Hd2];
__device__ __nv_bfloat162 g_XWc[(size_t)NCn * Hd2];
__device__ __nv_bfloat162 g_P1c[(size_t)NCn * Hd2];
__device__ float g_dinv_r[NRn];
__device__ float g_dinv_c[NCn];
__device__ float g_Wf_r[Dd * Hd];
__device__ float g_Wf_c[Dd * Hd];
__device__ __nv_bfloat16 g_WtHiR[Hd * Dd];
__device__ __nv_bfloat16 g_WtLoR[Hd * Dd];
__device__ __nv_bfloat16 g_WtHiC[Hd * Dd];
__device__ __nv_bfloat16 g_WtLoC[Hd * Dd];
__device__ float g_pooled_r[Bsz * Hd];
__device__ float g_pooledG[Gn * Hd];
__device__ float g_graphs[Gn * Hd];
__device__ float g_reps[Bsz * 5 * Hd];
__device__ float g_hmid[Bsz * Hd];
// CSR scratch
__device__ int g_cnt_r[NRn];
__device__ int g_cnt_c[NCn];
__device__ int g_rowoff_r[NRn + 1];
__device__ int g_rowoff_c[NCn + 1];
__device__ int g_esrc_r[ERn];
__device__ int g_esrc_c[ECn];
__device__ int g_bsum[512];

// ---------------- small utility kernels ----------------
__global__ void filli_kernel(int* p, int n, int v) {
    int i = blockIdx.x * blockDim.x + threadIdx.x;
    if (i < n) p[i] = v;
}

__global__ void count_kernel(const int* __restrict__ dst, int* __restrict__ cnt, int E) {
    int e = blockIdx.x * blockDim.x + threadIdx.x;
    if (e < E) atomicAdd(&cnt[dst[e]], 1);
}

__global__ void dinv_kernel(const int* __restrict__ cnt, float* __restrict__ dinv, int n) {
    int i = blockIdx.x * blockDim.x + threadIdx.x;
    if (i < n) dinv[i] = rsqrtf((float)(cnt[i] + 1));
}

// ---------------- multi-block exclusive scan ----------------
__global__ void scan_blocksum_kernel(const int* __restrict__ cnt, int* __restrict__ bsum, int n) {
    __shared__ int sh[256];
    int tid = threadIdx.x;
    int i = blockIdx.x * 256 + tid;
    sh[tid] = (i < n) ? cnt[i] : 0;
    __syncthreads();
    for (int off = 128; off > 0; off >>= 1) {
        if (tid < off) sh[tid] += sh[tid + off];
        __syncthreads();
    }
    if (tid == 0) bsum[blockIdx.x] = sh[0];
}

__global__ void scan_bsum_kernel(int* __restrict__ bsum, int* __restrict__ rowoff, int nb, int n) {
    __shared__ int sh[512];
    int tid = threadIdx.x;  // 512
    int v = (tid < nb) ? bsum[tid] : 0;
    sh[tid] = v;
    __syncthreads();
    for (int off = 1; off < 512; off <<= 1) {
        int t = (tid >= off) ? sh[tid - off] : 0;
        __syncthreads();
        sh[tid] += t;
        __syncthreads();
    }
    if (tid < nb) bsum[tid] = sh[tid] - v;   // exclusive
    if (tid == 511) rowoff[n] = sh[511];     // total
}

__global__ void scan_final_kernel(const int* __restrict__ cnt, const int* __restrict__ bsum,
                                  int* __restrict__ rowoff, int n) {
    __shared__ int sh[256];
    int tid = threadIdx.x;
    int i = blockIdx.x * 256 + tid;
    int v = (i < n) ? cnt[i] : 0;
    sh[tid] = v;
    __syncthreads();
    for (int off = 1; off < 256; off <<= 1) {
        int t = (tid >= off) ? sh[tid - off] : 0;
        __syncthreads();
        sh[tid] += t;
        __syncthreads();
    }
    if (i < n) rowoff[i] = bsum[blockIdx.x] + sh[tid] - v;
}

__global__ void scatter_kernel(const int* __restrict__ src, const int* __restrict__ dst,
                               const int* __restrict__ rowoff, int* __restrict__ cursor,
                               int* __restrict__ esrc, int E) {
    int e = blockIdx.x * blockDim.x + threadIdx.x;
    if (e < E) {
        int d = dst[e];
        int pos = rowoff[d] + atomicAdd(&cursor[d], 1);
        esrc[pos] = src[e];
    }
}

// ---------------- bf16 CSR gather propagation (1 node/block, 128 threads) ----------------
__device__ __forceinline__ float2 bf2f(const __nv_bfloat162 v) { return __bfloat1622float2(v); }

// layer 1: out[n] = dinv[n]*( in[n]*dinv[n] + sum in[s]*dinv[s] ), no relu on input
__global__ __launch_bounds__(128) void gather_bf16_kernel(
    const __nv_bfloat162* __restrict__ in, __nv_bfloat162* __restrict__ out,
    const int* __restrict__ rowoff, const int* __restrict__ esrc,
    const float* __restrict__ dinv)
{
    int n = blockIdx.x;
    int j = threadIdx.x;            // col pair 0..127
    int beg = __ldg(&rowoff[n]), end = __ldg(&rowoff[n + 1]);
    float di = __ldg(&dinv[n]);
    float2 v = bf2f(in[(size_t)n * Hd2 + j]);
    float ax = v.x * di, ay = v.y * di;
    int e = beg;
    for (; e + 4 <= end; e += 4) {
        int s0 = __ldg(&esrc[e]);
        int s1 = __ldg(&esrc[e + 1]);
        int s2 = __ldg(&esrc[e + 2]);
        int s3 = __ldg(&esrc[e + 3]);
        float w0 = __ldg(&dinv[s0]), w1 = __ldg(&dinv[s1]);
        float w2 = __ldg(&dinv[s2]), w3 = __ldg(&dinv[s3]);
        float2 x0 = bf2f(in[(size_t)s0 * Hd2 + j]);
        float2 x1 = bf2f(in[(size_t)s1 * Hd2 + j]);
        float2 x2 = bf2f(in[(size_t)s2 * Hd2 + j]);
        float2 x3 = bf2f(in[(size_t)s3 * Hd2 + j]);
        ax += x0.x * w0 + x1.x * w1 + x2.x * w2 + x3.x * w3;
        ay += x0.y * w0 + x1.y * w1 + x2.y * w2 + x3.y * w3;
    }
    for (; e < end; e++) {
        int s0 = __ldg(&esrc[e]);
        float w0 = __ldg(&dinv[s0]);
        float2 x0 = bf2f(in[(size_t)s0 * Hd2 + j]);
        ax += x0.x * w0;
        ay += x0.y * w0;
    }
    out[(size_t)n * Hd2 + j] = __floats2bfloat162_rn(ax * di, ay * di);
}

// layer 2 + pooling: relu applied on reads; result atomically added to fp32 pool[batch[n]]
__global__ __launch_bounds__(128) void gather_pool_bf16_kernel(
    const __nv_bfloat162* __restrict__ in,
    const int* __restrict__ rowoff, const int* __restrict__ esrc,
    const float* __restrict__ dinv, const int* __restrict__ batch,
    float* __restrict__ pool)
{
    int n = blockIdx.x;
    int j = threadIdx.x;
    int beg = __ldg(&rowoff[n]), end = __ldg(&rowoff[n + 1]);
    float di = __ldg(&dinv[n]);
    float2 v = bf2f(in[(size_t)n * Hd2 + j]);
    v.x = fmaxf(v.x, 0.f); v.y = fmaxf(v.y, 0.f);
    float ax = v.x * di, ay = v.y * di;
    int e = beg;
    for (; e + 4 <= end; e += 4) {
        int s0 = __ldg(&esrc[e]);
        int s1 = __ldg(&esrc[e + 1]);
        int s2 = __ldg(&esrc[e + 2]);
        int s3 = __ldg(&esrc[e + 3]);
        float w0 = __ldg(&dinv[s0]), w1 = __ldg(&dinv[s1]);
        float w2 = __ldg(&dinv[s2]), w3 = __ldg(&dinv[s3]);
        float2 x0 = bf2f(in[(size_t)s0 * Hd2 + j]);
        float2 x1 = bf2f(in[(size_t)s1 * Hd2 + j]);
        float2 x2 = bf2f(in[(size_t)s2 * Hd2 + j]);
        float2 x3 = bf2f(in[(size_t)s3 * Hd2 + j]);
        ax += fmaxf(x0.x, 0.f) * w0 + fmaxf(x1.x, 0.f) * w1
            + fmaxf(x2.x, 0.f) * w2 + fmaxf(x3.x, 0.f) * w3;
        ay += fmaxf(x0.y, 0.f) * w0 + fmaxf(x1.y, 0.f) * w1
            + fmaxf(x2.y, 0.f) * w2 + fmaxf(x3.y, 0.f) * w3;
    }
    for (; e < end; e++) {
        int s0 = __ldg(&esrc[e]);
        float w0 = __ldg(&dinv[s0]);
        float2 x0 = bf2f(in[(size_t)s0 * Hd2 + j]);
        ax += fmaxf(x0.x, 0.f) * w0;
        ay += fmaxf(x0.y, 0.f) * w0;
    }
    int b = __ldg(&batch[n]);
    float* p = &pool[(size_t)b * Hd + j * 2];
    atomicAdd(p + 0, ax * di);
    atomicAdd(p + 1, ay * di);
}

__device__ __forceinline__ int lower_bound_dev(const int* a, int n, int v) {
    int lo = 0, hi = n;
    while (lo < hi) { int mid = (lo + hi) >> 1; if (a[mid] < v) lo = mid + 1; else hi = mid; }
    return lo;
}

__global__ void pool_partial_kernel(const float* __restrict__ x, const int* __restrict__ seg,
                                    int n, float* __restrict__ acc, int chunks) {
    int b = blockIdx.x;
    int chunk = blockIdx.y;
    int start = lower_bound_dev(seg, n, b);
    int end   = lower_bound_dev(seg, n, b + 1);
    int len = end - start;
    if (len <= 0) return;
    int per = (len + chunks - 1) / chunks;
    int s0 = start + chunk * per;
    int s1 = s0 + per; if (s1 > end) s1 = end;
    if (s0 >= s1) return;
    int j = threadIdx.x;
    float a = 0.0f;
    for (int r = s0; r < s1; r++) a += x[(size_t)r * Hd + j];
    atomicAdd(&acc[b * Hd + j], a);
}

__global__ void pool_div_kernel(const float* __restrict__ acc, const int* __restrict__ seg,
                                int n, float* __restrict__ dst, int ld) {
    int b = blockIdx.x;
    int j = threadIdx.x;
    int cnt = lower_bound_dev(seg, n, b + 1) - lower_bound_dev(seg, n, b);
    float c = fmaxf((float)cnt, 1.0f);
    dst[(size_t)b * ld + j] = acc[b * Hd + j] / c;
}

// ---------------- transpose + bf16 split of fused weight ----------------
__global__ void convtrans_kernel(const float* __restrict__ W,
                                 __nv_bfloat16* __restrict__ oHi,
                                 __nv_bfloat16* __restrict__ oLo) {
    int i = blockIdx.x * blockDim.x + threadIdx.x;
    if (i >= Dd * Hd) return;
    int k = i / Hd, n = i % Hd;
    float f = W[i];
    __nv_bfloat16 h = __float2bfloat16(f);
    float r = f - __bfloat162float(h);
    oHi[(size_t)n * Dd + k] = h;
    oLo[(size_t)n * Dd + k] = __float2bfloat16(r);
}

// ---------------- tensor-core GEMM (bf16 split, 3 products), bf16 output ----------------
__device__ __forceinline__ void ldsm_x4(uint32_t r[4], const void* p) {
    uint32_t a = (uint32_t)__cvta_generic_to_shared(p);
    asm volatile("ldmatrix.sync.aligned.m8n8.x4.shared.b16 {%0,%1,%2,%3}, [%4];"
                 : "=r"(r[0]), "=r"(r[1]), "=r"(r[2]), "=r"(r[3]) : "r"(a));
}

__device__ __forceinline__ void mma_bf16(float acc[4], uint32_t a0, uint32_t a1,
                                         uint32_t a2, uint32_t a3,
                                         uint32_t b0, uint32_t b1) {
    asm volatile(
        "mma.sync.aligned.m16n8k16.row.col.f32.bf16.bf16.f32 "
        "{%0,%1,%2,%3},{%4,%5,%6,%7},{%8,%9},{%0,%1,%2,%3};"
        : "+f"(acc[0]), "+f"(acc[1]), "+f"(acc[2]), "+f"(acc[3])
        : "r"(a0), "r"(a1), "r"(a2), "r"(a3), "r"(b0), "r"(b1));
}

__global__ __launch_bounds__(256) void gemm_tc_kernel(
    const float* __restrict__ A,
    const __nv_bfloat16* __restrict__ BtHi,
    const __nv_bfloat16* __restrict__ BtLo,
    __nv_bfloat162* __restrict__ C, int M)
{
    const int K = Dd;
    const int LDS_STRIDE = 40;
    __shared__ __nv_bfloat16 AsH[128][LDS_STRIDE];
    __shared__ __nv_bfloat16 AsL[128][LDS_STRIDE];
    __shared__ __nv_bfloat16 BsH[128][LDS_STRIDE];
    __shared__ __nv_bfloat16 BsL[128][LDS_STRIDE];

    int tid = threadIdx.x;
    int warp = tid >> 5, lane = tid & 31;
    int bRow = blockIdx.y * 128, bCol = blockIdx.x * 128;
    int wm = (warp >> 2) * 64;
    int wn = (warp & 3) * 32;

    float acc[4][4][4];
#pragma unroll
    for (int a = 0; a < 4; a++)
#pragma unroll
        for (int b = 0; b < 4; b++)
#pragma unroll
            for (int c = 0; c < 4; c++) acc[a][b][c] = 0.0f;

    float4 aR[4];
    const float4 z4 = make_float4(0.f, 0.f, 0.f, 0.f);
#define LOAD_A(k0)                                                            \
    {                                                                         \
        _Pragma("unroll")                                                     \
        for (int l = 0; l < 4; l++) {                                         \
            int i = tid + l * 256;                                            \
            int r = i >> 3, c4 = (i & 7) * 4;                                 \
            int gr = bRow + r;                                                \
            aR[l] = (gr < M) ? *(const float4*)&A[(size_t)gr * K + (k0) + c4] \
                             : z4;                                            \
        }                                                                     \
    }

    LOAD_A(0);

    for (int it = 0; it < K / 32; it++) {
        int k0 = it * 32;
#pragma unroll
        for (int l = 0; l < 2; l++) {
            int i = tid + l * 256;
            int r = i >> 2, c8 = (i & 3) * 8;
            *(float4*)&BsH[r][c8] = *(const float4*)&BtHi[(size_t)(bCol + r) * K + k0 + c8];
            *(float4*)&BsL[r][c8] = *(const float4*)&BtLo[(size_t)(bCol + r) * K + k0 + c8];
        }
#pragma unroll
        for (int l = 0; l < 4; l++) {
            int i = tid + l * 256;
            int r = i >> 3, c4 = (i & 7) * 4;
            float f[4] = {aR[l].x, aR[l].y, aR[l].z, aR[l].w};
            __nv_bfloat16 h[4], lo[4];
#pragma unroll
            for (int j = 0; j < 4; j++) {
                h[j] = __float2bfloat16(f[j]);
                lo[j] = __float2bfloat16(f[j] - __bfloat162float(h[j]));
            }
            *(__nv_bfloat162*)&AsH[r][c4]     = __nv_bfloat162(h[0], h[1]);
            *(__nv_bfloat162*)&AsH[r][c4 + 2] = __nv_bfloat162(h[2], h[3]);
            *(__nv_bfloat162*)&AsL[r][c4]     = __nv_bfloat162(lo[0], lo[1]);
            *(__nv_bfloat162*)&AsL[r][c4 + 2] = __nv_bfloat162(lo[2], lo[3]);
        }
        __syncthreads();

        if (it < K / 32 - 1) LOAD_A(k0 + 32);

        int mt = lane >> 3, ri = lane & 7;
#pragma unroll
        for (int ks = 0; ks < 2; ks++) {
            int colOff = ks * 16 + (mt >> 1) * 8;
            uint32_t aH[4][4], aL[4][4], bH[2][4], bL[2][4];
#pragma unroll
            for (int mi = 0; mi < 4; mi++) {
                int row = wm + mi * 16 + (mt & 1) * 8 + ri;
                ldsm_x4(aH[mi], &AsH[row][colOff]);
                ldsm_x4(aL[mi], &AsL[row][colOff]);
            }
#pragma unroll
            for (int bj = 0; bj < 2; bj++) {
                int row = wn + bj * 16 + (mt & 1) * 8 + ri;
                ldsm_x4(bH[bj], &BsH[row][colOff]);
                ldsm_x4(bL[bj], &BsL[row][colOff]);
            }
#pragma unroll
            for (int mi = 0; mi < 4; mi++)
#pragma unroll
                for (int nj = 0; nj < 4; nj++) {
                    int bj = nj >> 1, s = nj & 1;
                    mma_bf16(acc[mi][nj], aH[mi][0], aH[mi][1], aH[mi][2], aH[mi][3],
                             bH[bj][s], bH[bj][s + 2]);
                    mma_bf16(acc[mi][nj], aH[mi][0], aH[mi][1], aH[mi][2], aH[mi][3],
                             bL[bj][s], bL[bj][s + 2]);
                    mma_bf16(acc[mi][nj], aL[mi][0], aL[mi][1], aL[mi][2], aL[mi][3],
                             bH[bj][s], bH[bj][s + 2]);
                }
        }
        __syncthreads();
    }

    int g = lane >> 2, t = lane & 3;
#pragma unroll
    for (int mi = 0; mi < 4; mi++)
#pragma unroll
        for (int nj = 0; nj < 4; nj++) {
            int row = bRow + wm + mi * 16 + g;
            int colp = (bCol + wn + nj * 8 + t * 2) >> 1;   // bf16x2 pair index
            if (row < M)
                C[(size_t)row * Hd2 + colp] = __floats2bfloat162_rn(acc[mi][nj][0], acc[mi][nj][1]);
            if (row + 8 < M)
                C[(size_t)(row + 8) * Hd2 + colp] = __floats2bfloat162_rn(acc[mi][nj][2], acc[mi][nj][3]);
        }
#undef LOAD_A
}

// ---------------- small fp32 GEMM ----------------
__global__ __launch_bounds__(256) void sgemm64_kernel(const float* __restrict__ A, int lda,
                                                      const float* __restrict__ Bm,
                                                      const float* __restrict__ bias,
                                                      float* __restrict__ C, int ldc,
                                                      int M, int N, int K, int doRelu) {
    const int BM = 64, BN = 64, BK = 16, TM = 4, TN = 4;
    __shared__ float As[BK][BM];
    __shared__ float Bs[BK][BN];
    const int tid = threadIdx.x;
    const int bRow = blockIdx.y * BM;
    const int bCol = blockIdx.x * BN;
    const int tx = tid % 16;
    const int ty = tid / 16;

    float acc[TM][TN];
#pragma unroll
    for (int i = 0; i < TM; i++)
#pragma unroll
        for (int j = 0; j < TN; j++) acc[i][j] = 0.0f;

    for (int k0 = 0; k0 < K; k0 += BK) {
        {
            int i = tid;
            int r = i >> 2;
            int c4 = (i & 3) << 2;
            int grow = bRow + r;
            float4 v = make_float4(0.f, 0.f, 0.f, 0.f);
            if (grow < M) v = *reinterpret_cast<const float4*>(&A[(size_t)grow * lda + k0 + c4]);
            As[c4 + 0][r] = v.x; As[c4 + 1][r] = v.y; As[c4 + 2][r] = v.z; As[c4 + 3][r] = v.w;
        }
        {
            int i = tid;
            int r = i >> 4;
            int c = (i & 15) << 2;
            float4 v = *reinterpret_cast<const float4*>(&Bm[(size_t)(k0 + r) * N + bCol + c]);
            *reinterpret_cast<float4*>(&Bs[r][c]) = v;
        }
        __syncthreads();

        float ar[TM], br[TN];
#pragma unroll
        for (int kk = 0; kk < BK; kk++) {
#pragma unroll
            for (int i = 0; i < TM; i++) ar[i] = As[kk][ty * TM + i];
#pragma unroll
            for (int j = 0; j < TN; j++) br[j] = Bs[kk][tx * TN + j];
#pragma unroll
            for (int i = 0; i < TM; i++)
#pragma unroll
                for (int j = 0; j < TN; j++) acc[i][j] += ar[i] * br[j];
        }
        __syncthreads();
    }

#pragma unroll
    for (int i = 0; i < TM; i++) {
        int grow = bRow + ty * TM + i;
        if (grow >= M) continue;
#pragma unroll
        for (int j = 0; j < TN; j++) {
            int gcol = bCol + tx * TN + j;
            float v = acc[i][j];
            if (bias) v += bias[gcol];
            if (doRelu) v = fmaxf(v, 0.0f);
            C[(size_t)grow * ldc + gcol] = v;
        }
    }
}

// ---------------- head ----------------
__global__ void head_kernel(const float* __restrict__ h, const float* __restrict__ W2,
                            const float* __restrict__ b2, const int* __restrict__ label,
                            float* __restrict__ out, int out_size) {
    __shared__ float preds[Bsz][2];
    int tid = threadIdx.x;
    if (tid < Bsz * 2) {
        int r = tid >> 1, c = tid & 1;
        float s = b2[c];
        for (int k = 0; k < Hd; k++) s += h[r * Hd + k] * W2[k * 2 + c];
        preds[r][c] = s;
    }
    __syncthreads();
    if (tid < Bsz * 2 && tid < out_size) out[tid] = preds[tid >> 1][tid & 1];
    if (tid == 0 && out_size >= Bsz * 2 + 1) {
        float loss = 0.0f;
        for (int r = 0; r < Bsz; r++) {
            float a = preds[r][0], b = preds[r][1];
            float m = fmaxf(a, b);
            float lse = m + logf(expf(a - m) + expf(b - m));
            int y = label[r];
            loss += lse - (y ? b : a);
        }
        out[Bsz * 2] = loss / (float)Bsz;
    }
}

// ---------------- launch ----------------
extern "C" void kernel_launch(void* const* d_in, const int* in_sizes, int n_in,
                              void* d_out, int out_size) {
    const float* content  = (const float*)d_in[0];
    const float* video    = (const float*)d_in[1];
    const float* image    = (const float*)d_in[2];
    const float* repost_x = (const float*)d_in[3];
    const float* comment_x= (const float*)d_in[4];
    const float* W_text   = (const float*)d_in[5];
    const float* W_video  = (const float*)d_in[6];
    const float* W_image  = (const float*)d_in[7];
    const float* Wr1      = (const float*)d_in[8];
    const float* Wr2      = (const float*)d_in[9];
    const float* Wc1      = (const float*)d_in[10];
    const float* Wc2      = (const float*)d_in[11];
    const float* W1       = (const float*)d_in[12];
    const float* b1       = (const float*)d_in[13];
    const float* W2       = (const float*)d_in[14];
    const float* b2       = (const float*)d_in[15];
    const int* rei        = (const int*)d_in[16];
    const int* rbatch     = (const int*)d_in[17];
    const int* cei        = (const int*)d_in[18];
    const int* cbatch     = (const int*)d_in[19];
    const int* cgb        = (const int*)d_in[20];
    const int* label      = (const int*)d_in[21];
    float* out            = (float*)d_out;

    __nv_bfloat162 *pXWr, *pP1r, *pXWc, *pP1c;
    float *pDr, *pDc, *pWfr, *pWfc;
    float *pPoolR, *pPoolG, *pGraphs, *pReps, *pHmid;
    __nv_bfloat16 *pWtHiR, *pWtLoR, *pWtHiC, *pWtLoC;
    int *pCntR, *pCntC, *pRoR, *pRoC, *pEsR, *pEsC, *pBsum;
    cudaGetSymbolAddress((void**)&pXWr, g_XWr);
    cudaGetSymbolAddress((void**)&pP1r, g_P1r);
    cudaGetSymbolAddress((void**)&pXWc, g_XWc);
    cudaGetSymbolAddress((void**)&pP1c, g_P1c);
    cudaGetSymbolAddress((void**)&pDr, g_dinv_r);
    cudaGetSymbolAddress((void**)&pDc, g_dinv_c);
    cudaGetSymbolAddress((void**)&pWfr, g_Wf_r);
    cudaGetSymbolAddress((void**)&pWfc, g_Wf_c);
    cudaGetSymbolAddress((void**)&pWtHiR, g_WtHiR);
    cudaGetSymbolAddress((void**)&pWtLoR, g_WtLoR);
    cudaGetSymbolAddress((void**)&pWtHiC, g_WtHiC);
    cudaGetSymbolAddress((void**)&pWtLoC, g_WtLoC);
    cudaGetSymbolAddress((void**)&pPoolR, g_pooled_r);
    cudaGetSymbolAddress((void**)&pPoolG, g_pooledG);
    cudaGetSymbolAddress((void**)&pGraphs, g_graphs);
    cudaGetSymbolAddress((void**)&pReps, g_reps);
    cudaGetSymbolAddress((void**)&pHmid, g_hmid);
    cudaGetSymbolAddress((void**)&pCntR, g_cnt_r);
    cudaGetSymbolAddress((void**)&pCntC, g_cnt_c);
    cudaGetSymbolAddress((void**)&pRoR, g_rowoff_r);
    cudaGetSymbolAddress((void**)&pRoC, g_rowoff_c);
    cudaGetSymbolAddress((void**)&pEsR, g_esrc_r);
    cudaGetSymbolAddress((void**)&pEsC, g_esrc_c);
    cudaGetSymbolAddress((void**)&pBsum, g_bsum);

    const int* r_src = rei;            const int* r_dst = rei + ERn;
    const int* c_src = cei;            const int* c_dst = cei + ECn;

    const int NBr = (NRn + 255) / 256;
    const int NBc = (NCn + 255) / 256;

    // ---- CSR build: repost ----
    filli_kernel<<<NBr, 256>>>(pCntR, NRn, 0);
    count_kernel<<<(ERn + 255) / 256, 256>>>(r_dst, pCntR, ERn);
    dinv_kernel<<<NBr, 256>>>(pCntR, pDr, NRn);
    scan_blocksum_kernel<<<NBr, 256>>>(pCntR, pBsum, NRn);
    scan_bsum_kernel<<<1, 512>>>(pBsum, pRoR, NBr, NRn);
    scan_final_kernel<<<NBr, 256>>>(pCntR, pBsum, pRoR, NRn);
    filli_kernel<<<NBr, 256>>>(pCntR, NRn, 0);
    scatter_kernel<<<(ERn + 255) / 256, 256>>>(r_src, r_dst, pRoR, pCntR, pEsR, ERn);

    // ---- CSR build: comment ----
    filli_kernel<<<NBc, 256>>>(pCntC, NCn, 0);
    count_kernel<<<(ECn + 255) / 256, 256>>>(c_dst, pCntC, ECn);
    dinv_kernel<<<NBc, 256>>>(pCntC, pDc, NCn);
    scan_blocksum_kernel<<<NBc, 256>>>(pCntC, pBsum, NCn);
    scan_bsum_kernel<<<1, 512>>>(pBsum, pRoC, NBc, NCn);
    scan_final_kernel<<<NBc, 256>>>(pCntC, pBsum, pRoC, NCn);
    filli_kernel<<<NBc, 256>>>(pCntC, NCn, 0);
    scatter_kernel<<<(ECn + 255) / 256, 256>>>(c_src, c_dst, pRoC, pCntC, pEsC, ECn);

    // ---- fused first-layer weights + bf16 splits ----
    sgemm64_kernel<<<dim3(Hd / 64, Dd / 64), 256>>>(W_text, Hd, Wr1, nullptr, pWfr, Hd, Dd, Hd, Hd, 0);
    sgemm64_kernel<<<dim3(Hd / 64, Dd / 64), 256>>>(W_text, Hd, Wc1, nullptr, pWfc, Hd, Dd, Hd, Hd, 0);
    convtrans_kernel<<<(Dd * Hd + 255) / 256, 256>>>(pWfr, pWtHiR, pWtLoR);
    convtrans_kernel<<<(Dd * Hd + 255) / 256, 256>>>(pWfc, pWtHiC, pWtLoC);

    // ---- big GEMMs on tensor cores, bf16 output ----
    gemm_tc_kernel<<<dim3(2, (NRn + 127) / 128), 256>>>(repost_x, pWtHiR, pWtLoR, pXWr, NRn);
    gemm_tc_kernel<<<dim3(2, (NCn + 127) / 128), 256>>>(comment_x, pWtHiC, pWtLoC, pXWc, NCn);

    // ---- repost branch ----
    gather_bf16_kernel<<<NRn, 128>>>(pXWr, pP1r, pRoR, pEsR, pDr);
    cudaMemsetAsync(pPoolR, 0, (size_t)Bsz * Hd * sizeof(float));
    gather_pool_bf16_kernel<<<NRn, 128>>>(pP1r, pRoR, pEsR, pDr, rbatch, pPoolR);
    pool_div_kernel<<<Bsz, Hd>>>(pPoolR, rbatch, NRn, pPoolR, Hd);

    // ---- comment branch ----
    gather_bf16_kernel<<<NCn, 128>>>(pXWc, pP1c, pRoC, pEsC, pDc);
    cudaMemsetAsync(pPoolG, 0, (size_t)Gn * Hd * sizeof(float));
    gather_pool_bf16_kernel<<<NCn, 128>>>(pP1c, pRoC, pEsC, pDc, cbatch, pPoolG);
    pool_div_kernel<<<Gn, Hd>>>(pPoolG, cbatch, NCn, pPoolG, Hd);

    sgemm64_kernel<<<dim3(Hd / 64, Gn / 64), 256>>>(pPoolG, Hd, Wc2, nullptr, pGraphs, Hd, Gn, Hd, Hd, 0);
    cudaMemsetAsync(pHmid, 0, (size_t)Bsz * Hd * sizeof(float));
    pool_partial_kernel<<<dim3(Bsz, 2), Hd>>>(pGraphs, cgb, Gn, pHmid, 2);
    pool_div_kernel<<<Bsz, Hd>>>(pHmid, cgb, Gn, pReps + 2 * Hd, 5 * Hd);

    // ---- assemble reps [64, 1280] ----
    sgemm64_kernel<<<dim3(Hd / 64, 1), 256>>>(content, Dd, W_text, nullptr, pReps + 0 * Hd, 5 * Hd, Bsz, Hd, Dd, 0);
    sgemm64_kernel<<<dim3(Hd / 64, 1), 256>>>(pPoolR, Hd, Wr2, nullptr, pReps + 1 * Hd, 5 * Hd, Bsz, Hd, Hd, 0);
    sgemm64_kernel<<<dim3(Hd / 64, 1), 256>>>(video, Dd, W_video, nullptr, pReps + 3 * Hd, 5 * Hd, Bsz, Hd, Dd, 0);
    sgemm64_kernel<<<dim3(Hd / 64, 1), 256>>>(image, Dd, W_image, nullptr, pReps + 4 * Hd, 5 * Hd, Bsz, Hd, Dd, 0);

    // ---- MLP head ----
    sgemm64_kernel<<<dim3(Hd / 64, 1), 256>>>(pReps, 5 * Hd, W1, b1, pHmid, Hd, Bsz, Hd, 5 * Hd, 1);
    head_kernel<<<1, 128>>>(pHmid, W2, b2, label, out, out_size);
}

// round 7
// speedup vs baseline: 1.4450x; 1.2619x over previous
#include <cuda_runtime.h>
#include <cuda_bf16.h>
#include <math.h>
#include <stdint.h>

// ---------------- problem constants ----------------
#define Bsz 64
#define Hd  256
#define Dd  768
#define NRn 100000
#define ERn 400000
#define NCn 100000
#define ECn 300000
#define Gn  512
#define Hd2 (Hd / 2)

// ---------------- device scratch ----------------
__device__ __nv_bfloat162 g_XWr[(size_t)NRn * Hd2];
__device__ __nv_bfloat162 g_P1r[(size_t)NRn * Hd2];
__device__ __nv_bfloat162 g_XWc[(size_t)NCn * Hd2];
__device__ __nv_bfloat162 g_P1c[(size_t)NCn * Hd2];
__device__ float g_dinv_r[NRn];
__device__ float g_dinv_c[NCn];
__device__ float g_Wf_r[Dd * Hd];
__device__ float g_Wf_c[Dd * Hd];
__device__ __nv_bfloat16 g_WtHiR[Hd * Dd];
__device__ __nv_bfloat16 g_WtHiC[Hd * Dd];
__device__ float g_pooled_r[Bsz * Hd];
__device__ float g_pooledG[Gn * Hd];
__device__ float g_graphs[Gn * Hd];
__device__ float g_reps[Bsz * 5 * Hd];
__device__ float g_hmid[Bsz * Hd];
// CSR scratch
__device__ int g_cnt_r[NRn];
__device__ int g_cnt_c[NCn];
__device__ int g_rowoff_r[NRn + 1];
__device__ int g_rowoff_c[NCn + 1];
__device__ int g_esrc_r[ERn];
__device__ int g_esrc_c[ECn];
__device__ int g_bsum[512];

// ---------------- small utility kernels ----------------
__global__ void filli_kernel(int* p, int n, int v) {
    int i = blockIdx.x * blockDim.x + threadIdx.x;
    if (i < n) p[i] = v;
}

__global__ void count_kernel(const int* __restrict__ dst, int* __restrict__ cnt, int E) {
    int e = blockIdx.x * blockDim.x + threadIdx.x;
    if (e < E) atomicAdd(&cnt[dst[e]], 1);
}

__global__ void dinv_kernel(const int* __restrict__ cnt, float* __restrict__ dinv, int n) {
    int i = blockIdx.x * blockDim.x + threadIdx.x;
    if (i < n) dinv[i] = rsqrtf((float)(cnt[i] + 1));
}

// ---------------- multi-block exclusive scan ----------------
__global__ void scan_blocksum_kernel(const int* __restrict__ cnt, int* __restrict__ bsum, int n) {
    __shared__ int sh[256];
    int tid = threadIdx.x;
    int i = blockIdx.x * 256 + tid;
    sh[tid] = (i < n) ? cnt[i] : 0;
    __syncthreads();
    for (int off = 128; off > 0; off >>= 1) {
        if (tid < off) sh[tid] += sh[tid + off];
        __syncthreads();
    }
    if (tid == 0) bsum[blockIdx.x] = sh[0];
}

__global__ void scan_bsum_kernel(int* __restrict__ bsum, int* __restrict__ rowoff, int nb, int n) {
    __shared__ int sh[512];
    int tid = threadIdx.x;  // 512
    int v = (tid < nb) ? bsum[tid] : 0;
    sh[tid] = v;
    __syncthreads();
    for (int off = 1; off < 512; off <<= 1) {
        int t = (tid >= off) ? sh[tid - off] : 0;
        __syncthreads();
        sh[tid] += t;
        __syncthreads();
    }
    if (tid < nb) bsum[tid] = sh[tid] - v;   // exclusive
    if (tid == 511) rowoff[n] = sh[511];     // total
}

__global__ void scan_final_kernel(const int* __restrict__ cnt, const int* __restrict__ bsum,
                                  int* __restrict__ rowoff, int n) {
    __shared__ int sh[256];
    int tid = threadIdx.x;
    int i = blockIdx.x * 256 + tid;
    int v = (i < n) ? cnt[i] : 0;
    sh[tid] = v;
    __syncthreads();
    for (int off = 1; off < 256; off <<= 1) {
        int t = (tid >= off) ? sh[tid - off] : 0;
        __syncthreads();
        sh[tid] += t;
        __syncthreads();
    }
    if (i < n) rowoff[i] = bsum[blockIdx.x] + sh[tid] - v;
}

__global__ void scatter_kernel(const int* __restrict__ src, const int* __restrict__ dst,
                               const int* __restrict__ rowoff, int* __restrict__ cursor,
                               int* __restrict__ esrc, int E) {
    int e = blockIdx.x * blockDim.x + threadIdx.x;
    if (e < E) {
        int d = dst[e];
        int pos = rowoff[d] + atomicAdd(&cursor[d], 1);
        esrc[pos] = src[e];
    }
}

// ---------------- bf16 CSR gather propagation (1 node/block, 128 threads) ----------------
__device__ __forceinline__ float2 bf2f(const __nv_bfloat162 v) { return __bfloat1622float2(v); }

__global__ __launch_bounds__(128) void gather_bf16_kernel(
    const __nv_bfloat162* __restrict__ in, __nv_bfloat162* __restrict__ out,
    const int* __restrict__ rowoff, const int* __restrict__ esrc,
    const float* __restrict__ dinv)
{
    int n = blockIdx.x;
    int j = threadIdx.x;
    int beg = __ldg(&rowoff[n]), end = __ldg(&rowoff[n + 1]);
    float di = __ldg(&dinv[n]);
    float2 v = bf2f(in[(size_t)n * Hd2 + j]);
    float ax = v.x * di, ay = v.y * di;
    int e = beg;
    for (; e + 4 <= end; e += 4) {
        int s0 = __ldg(&esrc[e]);
        int s1 = __ldg(&esrc[e + 1]);
        int s2 = __ldg(&esrc[e + 2]);
        int s3 = __ldg(&esrc[e + 3]);
        float w0 = __ldg(&dinv[s0]), w1 = __ldg(&dinv[s1]);
        float w2 = __ldg(&dinv[s2]), w3 = __ldg(&dinv[s3]);
        float2 x0 = bf2f(in[(size_t)s0 * Hd2 + j]);
        float2 x1 = bf2f(in[(size_t)s1 * Hd2 + j]);
        float2 x2 = bf2f(in[(size_t)s2 * Hd2 + j]);
        float2 x3 = bf2f(in[(size_t)s3 * Hd2 + j]);
        ax += x0.x * w0 + x1.x * w1 + x2.x * w2 + x3.x * w3;
        ay += x0.y * w0 + x1.y * w1 + x2.y * w2 + x3.y * w3;
    }
    for (; e < end; e++) {
        int s0 = __ldg(&esrc[e]);
        float w0 = __ldg(&dinv[s0]);
        float2 x0 = bf2f(in[(size_t)s0 * Hd2 + j]);
        ax += x0.x * w0;
        ay += x0.y * w0;
    }
    out[(size_t)n * Hd2 + j] = __floats2bfloat162_rn(ax * di, ay * di);
}

__global__ __launch_bounds__(128) void gather_pool_bf16_kernel(
    const __nv_bfloat162* __restrict__ in,
    const int* __restrict__ rowoff, const int* __restrict__ esrc,
    const float* __restrict__ dinv, const int* __restrict__ batch,
    float* __restrict__ pool)
{
    int n = blockIdx.x;
    int j = threadIdx.x;
    int beg = __ldg(&rowoff[n]), end = __ldg(&rowoff[n + 1]);
    float di = __ldg(&dinv[n]);
    float2 v = bf2f(in[(size_t)n * Hd2 + j]);
    v.x = fmaxf(v.x, 0.f); v.y = fmaxf(v.y, 0.f);
    float ax = v.x * di, ay = v.y * di;
    int e = beg;
    for (; e + 4 <= end; e += 4) {
        int s0 = __ldg(&esrc[e]);
        int s1 = __ldg(&esrc[e + 1]);
        int s2 = __ldg(&esrc[e + 2]);
        int s3 = __ldg(&esrc[e + 3]);
        float w0 = __ldg(&dinv[s0]), w1 = __ldg(&dinv[s1]);
        float w2 = __ldg(&dinv[s2]), w3 = __ldg(&dinv[s3]);
        float2 x0 = bf2f(in[(size_t)s0 * Hd2 + j]);
        float2 x1 = bf2f(in[(size_t)s1 * Hd2 + j]);
        float2 x2 = bf2f(in[(size_t)s2 * Hd2 + j]);
        float2 x3 = bf2f(in[(size_t)s3 * Hd2 + j]);
        ax += fmaxf(x0.x, 0.f) * w0 + fmaxf(x1.x, 0.f) * w1
            + fmaxf(x2.x, 0.f) * w2 + fmaxf(x3.x, 0.f) * w3;
        ay += fmaxf(x0.y, 0.f) * w0 + fmaxf(x1.y, 0.f) * w1
            + fmaxf(x2.y, 0.f) * w2 + fmaxf(x3.y, 0.f) * w3;
    }
    for (; e < end; e++) {
        int s0 = __ldg(&esrc[e]);
        float w0 = __ldg(&dinv[s0]);
        float2 x0 = bf2f(in[(size_t)s0 * Hd2 + j]);
        ax += fmaxf(x0.x, 0.f) * w0;
        ay += fmaxf(x0.y, 0.f) * w0;
    }
    int b = __ldg(&batch[n]);
    float* p = &pool[(size_t)b * Hd + j * 2];
    atomicAdd(p + 0, ax * di);
    atomicAdd(p + 1, ay * di);
}

__device__ __forceinline__ int lower_bound_dev(const int* a, int n, int v) {
    int lo = 0, hi = n;
    while (lo < hi) { int mid = (lo + hi) >> 1; if (a[mid] < v) lo = mid + 1; else hi = mid; }
    return lo;
}

__global__ void pool_partial_kernel(const float* __restrict__ x, const int* __restrict__ seg,
                                    int n, float* __restrict__ acc, int chunks) {
    int b = blockIdx.x;
    int chunk = blockIdx.y;
    int start = lower_bound_dev(seg, n, b);
    int end   = lower_bound_dev(seg, n, b + 1);
    int len = end - start;
    if (len <= 0) return;
    int per = (len + chunks - 1) / chunks;
    int s0 = start + chunk * per;
    int s1 = s0 + per; if (s1 > end) s1 = end;
    if (s0 >= s1) return;
    int j = threadIdx.x;
    float a = 0.0f;
    for (int r = s0; r < s1; r++) a += x[(size_t)r * Hd + j];
    atomicAdd(&acc[b * Hd + j], a);
}

__global__ void pool_div_kernel(const float* __restrict__ acc, const int* __restrict__ seg,
                                int n, float* __restrict__ dst, int ld) {
    int b = blockIdx.x;
    int j = threadIdx.x;
    int cnt = lower_bound_dev(seg, n, b + 1) - lower_bound_dev(seg, n, b);
    float c = fmaxf((float)cnt, 1.0f);
    dst[(size_t)b * ld + j] = acc[b * Hd + j] / c;
}

// ---------------- transpose + bf16 convert of fused weight (hi only) ----------------
__global__ void convtrans_kernel(const float* __restrict__ W,
                                 __nv_bfloat16* __restrict__ oHi) {
    int i = blockIdx.x * blockDim.x + threadIdx.x;
    if (i >= Dd * Hd) return;
    int k = i / Hd, n = i % Hd;
    oHi[(size_t)n * Dd + k] = __float2bfloat16(W[i]);
}

// ---------------- tensor-core GEMM: single-product bf16, double-buffered ----------------
__device__ __forceinline__ void ldsm_x4(uint32_t r[4], const void* p) {
    uint32_t a = (uint32_t)__cvta_generic_to_shared(p);
    asm volatile("ldmatrix.sync.aligned.m8n8.x4.shared.b16 {%0,%1,%2,%3}, [%4];"
                 : "=r"(r[0]), "=r"(r[1]), "=r"(r[2]), "=r"(r[3]) : "r"(a));
}

__device__ __forceinline__ void mma_bf16(float acc[4], uint32_t a0, uint32_t a1,
                                         uint32_t a2, uint32_t a3,
                                         uint32_t b0, uint32_t b1) {
    asm volatile(
        "mma.sync.aligned.m16n8k16.row.col.f32.bf16.bf16.f32 "
        "{%0,%1,%2,%3},{%4,%5,%6,%7},{%8,%9},{%0,%1,%2,%3};"
        : "+f"(acc[0]), "+f"(acc[1]), "+f"(acc[2]), "+f"(acc[3])
        : "r"(a0), "r"(a1), "r"(a2), "r"(a3), "r"(b0), "r"(b1));
}

#define LDS_STRIDE 40
#define NITER (Dd / 32)   // 24

__global__ __launch_bounds__(256) void gemm_bf16_kernel(
    const float* __restrict__ A,                 // [M, 768] fp32 row-major
    const __nv_bfloat16* __restrict__ Bt,        // [256][768] bf16 (N-major)
    __nv_bfloat162* __restrict__ C, int M)       // [M, 128] bf16x2
{
    __shared__ __nv_bfloat16 As[2][128][LDS_STRIDE];
    __shared__ __nv_bfloat16 Bs[2][128][LDS_STRIDE];

    int tid = threadIdx.x;
    int warp = tid >> 5, lane = tid & 31;
    int bRow = blockIdx.y * 128, bCol = blockIdx.x * 128;
    int wm = (warp >> 2) * 64;
    int wn = (warp & 3) * 32;

    float acc[4][4][4];
#pragma unroll
    for (int a = 0; a < 4; a++)
#pragma unroll
        for (int b = 0; b < 4; b++)
#pragma unroll
            for (int c = 0; c < 4; c++) acc[a][b][c] = 0.0f;

    float4 aR[4];
    float4 bR[2];
    const float4 z4 = make_float4(0.f, 0.f, 0.f, 0.f);

#define LOAD_AB(k0)                                                           \
    {                                                                         \
        _Pragma("unroll")                                                     \
        for (int l = 0; l < 4; l++) {                                         \
            int i = tid + l * 256;                                            \
            int r = i >> 3, c4 = (i & 7) * 4;                                 \
            int gr = bRow + r;                                                \
            aR[l] = (gr < M) ? *(const float4*)&A[(size_t)gr * Dd + (k0) + c4]\
                             : z4;                                            \
        }                                                                     \
        _Pragma("unroll")                                                     \
        for (int l = 0; l < 2; l++) {                                         \
            int i = tid + l * 256;                                            \
            int r = i >> 2, c8 = (i & 3) * 8;                                 \
            bR[l] = *(const float4*)&Bt[(size_t)(bCol + r) * Dd + (k0) + c8]; \
        }                                                                     \
    }

#define STORE_AB(st)                                                          \
    {                                                                         \
        _Pragma("unroll")                                                     \
        for (int l = 0; l < 2; l++) {                                         \
            int i = tid + l * 256;                                            \
            int r = i >> 2, c8 = (i & 3) * 8;                                 \
            *(float4*)&Bs[st][r][c8] = bR[l];                                 \
        }                                                                     \
        _Pragma("unroll")                                                     \
        for (int l = 0; l < 4; l++) {                                         \
            int i = tid + l * 256;                                            \
            int r = i >> 3, c4 = (i & 7) * 4;                                 \
            float f[4] = {aR[l].x, aR[l].y, aR[l].z, aR[l].w};                \
            *(__nv_bfloat162*)&As[st][r][c4] =                                \
                __floats2bfloat162_rn(f[0], f[1]);                            \
            *(__nv_bfloat162*)&As[st][r][c4 + 2] =                            \
                __floats2bfloat162_rn(f[2], f[3]);                            \
        }                                                                     \
    }

    LOAD_AB(0);
    STORE_AB(0);
    LOAD_AB(32);
    __syncthreads();

    int mt = lane >> 3, ri = lane & 7;
    for (int it = 0; it < NITER; it++) {
        int cur = it & 1, nxt = cur ^ 1;
        if (it < NITER - 1) {
            STORE_AB(nxt);                        // consumes regs for chunk it+1
            if (it < NITER - 2) LOAD_AB((it + 2) * 32);
        }
#pragma unroll
        for (int ks = 0; ks < 2; ks++) {
            int colOff = ks * 16 + (mt >> 1) * 8;
            uint32_t aH[4][4], bH[2][4];
#pragma unroll
            for (int mi = 0; mi < 4; mi++) {
                int row = wm + mi * 16 + (mt & 1) * 8 + ri;
                ldsm_x4(aH[mi], &As[cur][row][colOff]);
            }
#pragma unroll
            for (int bj = 0; bj < 2; bj++) {
                int row = wn + bj * 16 + (mt & 1) * 8 + ri;
                ldsm_x4(bH[bj], &Bs[cur][row][colOff]);
            }
#pragma unroll
            for (int mi = 0; mi < 4; mi++)
#pragma unroll
                for (int nj = 0; nj < 4; nj++) {
                    int bj = nj >> 1, s = nj & 1;
                    mma_bf16(acc[mi][nj], aH[mi][0], aH[mi][1], aH[mi][2], aH[mi][3],
                             bH[bj][s], bH[bj][s + 2]);
                }
        }
        __syncthreads();
    }
#undef LOAD_AB
#undef STORE_AB

    // epilogue: bf16x2 output
    int g = lane >> 2, t = lane & 3;
#pragma unroll
    for (int mi = 0; mi < 4; mi++)
#pragma unroll
        for (int nj = 0; nj < 4; nj++) {
            int row = bRow + wm + mi * 16 + g;
            int colp = (bCol + wn + nj * 8 + t * 2) >> 1;
            if (row < M)
                C[(size_t)row * Hd2 + colp] = __floats2bfloat162_rn(acc[mi][nj][0], acc[mi][nj][1]);
            if (row + 8 < M)
                C[(size_t)(row + 8) * Hd2 + colp] = __floats2bfloat162_rn(acc[mi][nj][2], acc[mi][nj][3]);
        }
}

// ---------------- small fp32 GEMM ----------------
__global__ __launch_bounds__(256) void sgemm64_kernel(const float* __restrict__ A, int lda,
                                                      const float* __restrict__ Bm,
                                                      const float* __restrict__ bias,
                                                      float* __restrict__ C, int ldc,
                                                      int M, int N, int K, int doRelu) {
    const int BM = 64, BN = 64, BK = 16, TM = 4, TN = 4;
    __shared__ float As[BK][BM];
    __shared__ float Bs[BK][BN];
    const int tid = threadIdx.x;
    const int bRow = blockIdx.y * BM;
    const int bCol = blockIdx.x * BN;
    const int tx = tid % 16;
    const int ty = tid / 16;

    float acc[TM][TN];
#pragma unroll
    for (int i = 0; i < TM; i++)
#pragma unroll
        for (int j = 0; j < TN; j++) acc[i][j] = 0.0f;

    for (int k0 = 0; k0 < K; k0 += BK) {
        {
            int i = tid;
            int r = i >> 2;
            int c4 = (i & 3) << 2;
            int grow = bRow + r;
            float4 v = make_float4(0.f, 0.f, 0.f, 0.f);
            if (grow < M) v = *reinterpret_cast<const float4*>(&A[(size_t)grow * lda + k0 + c4]);
            As[c4 + 0][r] = v.x; As[c4 + 1][r] = v.y; As[c4 + 2][r] = v.z; As[c4 + 3][r] = v.w;
        }
        {
            int i = tid;
            int r = i >> 4;
            int c = (i & 15) << 2;
            float4 v = *reinterpret_cast<const float4*>(&Bm[(size_t)(k0 + r) * N + bCol + c]);
            *reinterpret_cast<float4*>(&Bs[r][c]) = v;
        }
        __syncthreads();

        float ar[TM], br[TN];
#pragma unroll
        for (int kk = 0; kk < BK; kk++) {
#pragma unroll
            for (int i = 0; i < TM; i++) ar[i] = As[kk][ty * TM + i];
#pragma unroll
            for (int j = 0; j < TN; j++) br[j] = Bs[kk][tx * TN + j];
#pragma unroll
            for (int i = 0; i < TM; i++)
#pragma unroll
                for (int j = 0; j < TN; j++) acc[i][j] += ar[i] * br[j];
        }
        __syncthreads();
    }

#pragma unroll
    for (int i = 0; i < TM; i++) {
        int grow = bRow + ty * TM + i;
        if (grow >= M) continue;
#pragma unroll
        for (int j = 0; j < TN; j++) {
            int gcol = bCol + tx * TN + j;
            float v = acc[i][j];
            if (bias) v += bias[gcol];
            if (doRelu) v = fmaxf(v, 0.0f);
            C[(size_t)grow * ldc + gcol] = v;
        }
    }
}

// ---------------- head ----------------
__global__ void head_kernel(const float* __restrict__ h, const float* __restrict__ W2,
                            const float* __restrict__ b2, const int* __restrict__ label,
                            float* __restrict__ out, int out_size) {
    __shared__ float preds[Bsz][2];
    int tid = threadIdx.x;
    if (tid < Bsz * 2) {
        int r = tid >> 1, c = tid & 1;
        float s = b2[c];
        for (int k = 0; k < Hd; k++) s += h[r * Hd + k] * W2[k * 2 + c];
        preds[r][c] = s;
    }
    __syncthreads();
    if (tid < Bsz * 2 && tid < out_size) out[tid] = preds[tid >> 1][tid & 1];
    if (tid == 0 && out_size >= Bsz * 2 + 1) {
        float loss = 0.0f;
        for (int r = 0; r < Bsz; r++) {
            float a = preds[r][0], b = preds[r][1];
            float m = fmaxf(a, b);
            float lse = m + logf(expf(a - m) + expf(b - m));
            int y = label[r];
            loss += lse - (y ? b : a);
        }
        out[Bsz * 2] = loss / (float)Bsz;
    }
}

// ---------------- launch ----------------
extern "C" void kernel_launch(void* const* d_in, const int* in_sizes, int n_in,
                              void* d_out, int out_size) {
    const float* content  = (const float*)d_in[0];
    const float* video    = (const float*)d_in[1];
    const float* image    = (const float*)d_in[2];
    const float* repost_x = (const float*)d_in[3];
    const float* comment_x= (const float*)d_in[4];
    const float* W_text   = (const float*)d_in[5];
    const float* W_video  = (const float*)d_in[6];
    const float* W_image  = (const float*)d_in[7];
    const float* Wr1      = (const float*)d_in[8];
    const float* Wr2      = (const float*)d_in[9];
    const float* Wc1      = (const float*)d_in[10];
    const float* Wc2      = (const float*)d_in[11];
    const float* W1       = (const float*)d_in[12];
    const float* b1       = (const float*)d_in[13];
    const float* W2       = (const float*)d_in[14];
    const float* b2       = (const float*)d_in[15];
    const int* rei        = (const int*)d_in[16];
    const int* rbatch     = (const int*)d_in[17];
    const int* cei        = (const int*)d_in[18];
    const int* cbatch     = (const int*)d_in[19];
    const int* cgb        = (const int*)d_in[20];
    const int* label      = (const int*)d_in[21];
    float* out            = (float*)d_out;

    __nv_bfloat162 *pXWr, *pP1r, *pXWc, *pP1c;
    float *pDr, *pDc, *pWfr, *pWfc;
    float *pPoolR, *pPoolG, *pGraphs, *pReps, *pHmid;
    __nv_bfloat16 *pWtHiR, *pWtHiC;
    int *pCntR, *pCntC, *pRoR, *pRoC, *pEsR, *pEsC, *pBsum;
    cudaGetSymbolAddress((void**)&pXWr, g_XWr);
    cudaGetSymbolAddress((void**)&pP1r, g_P1r);
    cudaGetSymbolAddress((void**)&pXWc, g_XWc);
    cudaGetSymbolAddress((void**)&pP1c, g_P1c);
    cudaGetSymbolAddress((void**)&pDr, g_dinv_r);
    cudaGetSymbolAddress((void**)&pDc, g_dinv_c);
    cudaGetSymbolAddress((void**)&pWfr, g_Wf_r);
    cudaGetSymbolAddress((void**)&pWfc, g_Wf_c);
    cudaGetSymbolAddress((void**)&pWtHiR, g_WtHiR);
    cudaGetSymbolAddress((void**)&pWtHiC, g_WtHiC);
    cudaGetSymbolAddress((void**)&pPoolR, g_pooled_r);
    cudaGetSymbolAddress((void**)&pPoolG, g_pooledG);
    cudaGetSymbolAddress((void**)&pGraphs, g_graphs);
    cudaGetSymbolAddress((void**)&pReps, g_reps);
    cudaGetSymbolAddress((void**)&pHmid, g_hmid);
    cudaGetSymbolAddress((void**)&pCntR, g_cnt_r);
    cudaGetSymbolAddress((void**)&pCntC, g_cnt_c);
    cudaGetSymbolAddress((void**)&pRoR, g_rowoff_r);
    cudaGetSymbolAddress((void**)&pRoC, g_rowoff_c);
    cudaGetSymbolAddress((void**)&pEsR, g_esrc_r);
    cudaGetSymbolAddress((void**)&pEsC, g_esrc_c);
    cudaGetSymbolAddress((void**)&pBsum, g_bsum);

    const int* r_src = rei;            const int* r_dst = rei + ERn;
    const int* c_src = cei;            const int* c_dst = cei + ECn;

    const int NBr = (NRn + 255) / 256;
    const int NBc = (NCn + 255) / 256;

    // ---- weight prep + big bf16 TC GEMMs (repost GEMM at launch index 3 for ncu) ----
    sgemm64_kernel<<<dim3(Hd / 64, Dd / 64), 256>>>(W_text, Hd, Wr1, nullptr, pWfr, Hd, Dd, Hd, Hd, 0);
    convtrans_kernel<<<(Dd * Hd + 255) / 256, 256>>>(pWfr, pWtHiR);
    sgemm64_kernel<<<dim3(Hd / 64, Dd / 64), 256>>>(W_text, Hd, Wc1, nullptr, pWfc, Hd, Dd, Hd, Hd, 0);
    gemm_bf16_kernel<<<dim3(2, (NRn + 127) / 128), 256>>>(repost_x, pWtHiR, pXWr, NRn);
    convtrans_kernel<<<(Dd * Hd + 255) / 256, 256>>>(pWfc, pWtHiC);
    gemm_bf16_kernel<<<dim3(2, (NCn + 127) / 128), 256>>>(comment_x, pWtHiC, pXWc, NCn);

    // ---- CSR build: repost ----
    filli_kernel<<<NBr, 256>>>(pCntR, NRn, 0);
    count_kernel<<<(ERn + 255) / 256, 256>>>(r_dst, pCntR, ERn);
    dinv_kernel<<<NBr, 256>>>(pCntR, pDr, NRn);
    scan_blocksum_kernel<<<NBr, 256>>>(pCntR, pBsum, NRn);
    scan_bsum_kernel<<<1, 512>>>(pBsum, pRoR, NBr, NRn);
    scan_final_kernel<<<NBr, 256>>>(pCntR, pBsum, pRoR, NRn);
    filli_kernel<<<NBr, 256>>>(pCntR, NRn, 0);
    scatter_kernel<<<(ERn + 255) / 256, 256>>>(r_src, r_dst, pRoR, pCntR, pEsR, ERn);

    // ---- CSR build: comment ----
    filli_kernel<<<NBc, 256>>>(pCntC, NCn, 0);
    count_kernel<<<(ECn + 255) / 256, 256>>>(c_dst, pCntC, ECn);
    dinv_kernel<<<NBc, 256>>>(pCntC, pDc, NCn);
    scan_blocksum_kernel<<<NBc, 256>>>(pCntC, pBsum, NCn);
    scan_bsum_kernel<<<1, 512>>>(pBsum, pRoC, NBc, NCn);
    scan_final_kernel<<<NBc, 256>>>(pCntC, pBsum, pRoC, NCn);
    filli_kernel<<<NBc, 256>>>(pCntC, NCn, 0);
    scatter_kernel<<<(ECn + 255) / 256, 256>>>(c_src, c_dst, pRoC, pCntC, pEsC, ECn);

    // ---- repost branch ----
    gather_bf16_kernel<<<NRn, 128>>>(pXWr, pP1r, pRoR, pEsR, pDr);
    cudaMemsetAsync(pPoolR, 0, (size_t)Bsz * Hd * sizeof(float));
    gather_pool_bf16_kernel<<<NRn, 128>>>(pP1r, pRoR, pEsR, pDr, rbatch, pPoolR);
    pool_div_kernel<<<Bsz, Hd>>>(pPoolR, rbatch, NRn, pPoolR, Hd);

    // ---- comment branch ----
    gather_bf16_kernel<<<NCn, 128>>>(pXWc, pP1c, pRoC, pEsC, pDc);
    cudaMemsetAsync(pPoolG, 0, (size_t)Gn * Hd * sizeof(float));
    gather_pool_bf16_kernel<<<NCn, 128>>>(pP1c, pRoC, pEsC, pDc, cbatch, pPoolG);
    pool_div_kernel<<<Gn, Hd>>>(pPoolG, cbatch, NCn, pPoolG, Hd);

    sgemm64_kernel<<<dim3(Hd / 64, Gn / 64), 256>>>(pPoolG, Hd, Wc2, nullptr, pGraphs, Hd, Gn, Hd, Hd, 0);
    cudaMemsetAsync(pHmid, 0, (size_t)Bsz * Hd * sizeof(float));
    pool_partial_kernel<<<dim3(Bsz, 2), Hd>>>(pGraphs, cgb, Gn, pHmid, 2);
    pool_div_kernel<<<Bsz, Hd>>>(pHmid, cgb, Gn, pReps + 2 * Hd, 5 * Hd);

    // ---- assemble reps [64, 1280] ----
    sgemm64_kernel<<<dim3(Hd / 64, 1), 256>>>(content, Dd, W_text, nullptr, pReps + 0 * Hd, 5 * Hd, Bsz, Hd, Dd, 0);
    sgemm64_kernel<<<dim3(Hd / 64, 1), 256>>>(pPoolR, Hd, Wr2, nullptr, pReps + 1 * Hd, 5 * Hd, Bsz, Hd, Hd, 0);
    sgemm64_kernel<<<dim3(Hd / 64, 1), 256>>>(video, Dd, W_video, nullptr, pReps + 3 * Hd, 5 * Hd, Bsz, Hd, Dd, 0);
    sgemm64_kernel<<<dim3(Hd / 64, 1), 256>>>(image, Dd, W_image, nullptr, pReps + 4 * Hd, 5 * Hd, Bsz, Hd, Dd, 0);

    // ---- MLP head ----
    sgemm64_kernel<<<dim3(Hd / 64, 1), 256>>>(pReps, 5 * Hd, W1, b1, pHmid, Hd, Bsz, Hd, 5 * Hd, 1);
    head_kernel<<<1, 128>>>(pHmid, W2, b2, label, out, out_size);
}

// round 8
// speedup vs baseline: 1.6853x; 1.1664x over previous
#include <cuda_runtime.h>
#include <cuda_bf16.h>
#include <math.h>
#include <stdint.h>

// ---------------- problem constants ----------------
#define Bsz 64
#define Hd  256
#define Dd  768
#define NRn 100000
#define ERn 400000
#define NCn 100000
#define ECn 300000
#define Gn  512
#define Hd2 (Hd / 2)

// ---------------- device scratch ----------------
__device__ __nv_bfloat162 g_XWr[(size_t)NRn * Hd2];
__device__ __nv_bfloat162 g_P1r[(size_t)NRn * Hd2];
__device__ __nv_bfloat162 g_XWc[(size_t)NCn * Hd2];
__device__ __nv_bfloat162 g_P1c[(size_t)NCn * Hd2];
__device__ float g_dinv_r[NRn];
__device__ float g_dinv_c[NCn];
__device__ float g_Wf_r[Dd * Hd];
__device__ float g_Wf_c[Dd * Hd];
__device__ __nv_bfloat16 g_WtHiR[Hd * Dd];
__device__ __nv_bfloat16 g_WtHiC[Hd * Dd];
__device__ float g_pooled_r[Bsz * Hd];
__device__ float g_pooledG[Gn * Hd];
__device__ float g_graphs[Gn * Hd];
__device__ float g_reps[Bsz * 5 * Hd];
__device__ float g_hmid[Bsz * Hd];
// CSR scratch
__device__ int g_cnt_r[NRn];
__device__ int g_cnt_c[NCn];
__device__ int g_rowoff_r[NRn + 1];
__device__ int g_rowoff_c[NCn + 1];
__device__ int2 g_ew_r[ERn];     // {src, bits(dinv[src])}
__device__ int2 g_ew_c[ECn];
__device__ int g_bsum2[1024];    // [2][512]

// ---------------- CSR build (both graphs per launch) ----------------
__global__ void count2_kernel(const int* __restrict__ dstR, const int* __restrict__ dstC,
                              int* __restrict__ cntR, int* __restrict__ cntC) {
    int e = blockIdx.x * blockDim.x + threadIdx.x;
    if (e < ERn) atomicAdd(&cntR[dstR[e]], 1);
    if (e < ECn) atomicAdd(&cntC[dstC[e]], 1);
}

__global__ void dinv2_kernel(const int* __restrict__ cntR, const int* __restrict__ cntC,
                             float* __restrict__ dR, float* __restrict__ dC) {
    int i = blockIdx.x * blockDim.x + threadIdx.x;
    if (i < NRn) dR[i] = rsqrtf((float)(cntR[i] + 1));
    if (i < NCn) dC[i] = rsqrtf((float)(cntC[i] + 1));
}

__global__ void scan_blocksum2_kernel(const int* __restrict__ cntR, const int* __restrict__ cntC,
                                      int* __restrict__ bsum2, int n) {
    __shared__ int sh[256];
    const int* cnt = blockIdx.y ? cntC : cntR;
    int* bsum = bsum2 + blockIdx.y * 512;
    int tid = threadIdx.x;
    int i = blockIdx.x * 256 + tid;
    sh[tid] = (i < n) ? cnt[i] : 0;
    __syncthreads();
    for (int off = 128; off > 0; off >>= 1) {
        if (tid < off) sh[tid] += sh[tid + off];
        __syncthreads();
    }
    if (tid == 0) bsum[blockIdx.x] = sh[0];
}

__global__ void scan_bsum2_kernel(int* __restrict__ bsum2, int* __restrict__ roR,
                                  int* __restrict__ roC, int nb, int n) {
    __shared__ int sh[512];
    int* bsum = bsum2 + blockIdx.y * 512;
    int* rowoff = blockIdx.y ? roC : roR;
    int tid = threadIdx.x;  // 512
    int v = (tid < nb) ? bsum[tid] : 0;
    sh[tid] = v;
    __syncthreads();
    for (int off = 1; off < 512; off <<= 1) {
        int t = (tid >= off) ? sh[tid - off] : 0;
        __syncthreads();
        sh[tid] += t;
        __syncthreads();
    }
    if (tid < nb) bsum[tid] = sh[tid] - v;   // exclusive
    if (tid == 511) rowoff[n] = sh[511];     // total
}

__global__ void scan_final2_kernel(const int* __restrict__ cntR, const int* __restrict__ cntC,
                                   const int* __restrict__ bsum2,
                                   int* __restrict__ roR, int* __restrict__ roC, int n) {
    __shared__ int sh[256];
    const int* cnt = blockIdx.y ? cntC : cntR;
    const int* bsum = bsum2 + blockIdx.y * 512;
    int* rowoff = blockIdx.y ? roC : roR;
    int tid = threadIdx.x;
    int i = blockIdx.x * 256 + tid;
    int v = (i < n) ? cnt[i] : 0;
    sh[tid] = v;
    __syncthreads();
    for (int off = 1; off < 256; off <<= 1) {
        int t = (tid >= off) ? sh[tid - off] : 0;
        __syncthreads();
        sh[tid] += t;
        __syncthreads();
    }
    if (i < n) rowoff[i] = bsum[blockIdx.x] + sh[tid] - v;
}

__global__ void scatter2_kernel(
    const int* __restrict__ srcR, const int* __restrict__ dstR,
    const int* __restrict__ roR, int* __restrict__ curR,
    const float* __restrict__ dR, int2* __restrict__ ewR,
    const int* __restrict__ srcC, const int* __restrict__ dstC,
    const int* __restrict__ roC, int* __restrict__ curC,
    const float* __restrict__ dC, int2* __restrict__ ewC)
{
    int e = blockIdx.x * blockDim.x + threadIdx.x;
    if (blockIdx.y == 0) {
        if (e < ERn) {
            int d = dstR[e], s = srcR[e];
            int pos = roR[d] + atomicAdd(&curR[d], 1);
            ewR[pos] = make_int2(s, __float_as_int(__ldg(&dR[s])));
        }
    } else {
        if (e < ECn) {
            int d = dstC[e], s = srcC[e];
            int pos = roC[d] + atomicAdd(&curC[d], 1);
            ewC[pos] = make_int2(s, __float_as_int(__ldg(&dC[s])));
        }
    }
}

// ---------------- merged bf16 CSR gather (layer 1, both graphs) ----------------
__device__ __forceinline__ float2 bf2f(const __nv_bfloat162 v) { return __bfloat1622float2(v); }

__global__ __launch_bounds__(128) void gather1_kernel(
    const __nv_bfloat162* __restrict__ inR, __nv_bfloat162* __restrict__ outR,
    const int* __restrict__ roR, const int2* __restrict__ ewR, const float* __restrict__ dR,
    const __nv_bfloat162* __restrict__ inC, __nv_bfloat162* __restrict__ outC,
    const int* __restrict__ roC, const int2* __restrict__ ewC, const float* __restrict__ dC)
{
    int n = blockIdx.x;
    const __nv_bfloat162* in; __nv_bfloat162* out; const int* ro; const int2* ew; const float* dv;
    if (n < NRn) { in = inR; out = outR; ro = roR; ew = ewR; dv = dR; }
    else { n -= NRn; in = inC; out = outC; ro = roC; ew = ewC; dv = dC; }

    int j = threadIdx.x;
    int beg = __ldg(&ro[n]), end = __ldg(&ro[n + 1]);
    float di = __ldg(&dv[n]);
    float2 v = bf2f(in[(size_t)n * Hd2 + j]);
    float ax = v.x * di, ay = v.y * di;
    int e = beg;
    for (; e + 4 <= end; e += 4) {
        int2 p0 = __ldg(&ew[e]);
        int2 p1 = __ldg(&ew[e + 1]);
        int2 p2 = __ldg(&ew[e + 2]);
        int2 p3 = __ldg(&ew[e + 3]);
        float2 x0 = bf2f(in[(size_t)p0.x * Hd2 + j]);
        float2 x1 = bf2f(in[(size_t)p1.x * Hd2 + j]);
        float2 x2 = bf2f(in[(size_t)p2.x * Hd2 + j]);
        float2 x3 = bf2f(in[(size_t)p3.x * Hd2 + j]);
        float w0 = __int_as_float(p0.y), w1 = __int_as_float(p1.y);
        float w2 = __int_as_float(p2.y), w3 = __int_as_float(p3.y);
        ax += x0.x * w0 + x1.x * w1 + x2.x * w2 + x3.x * w3;
        ay += x0.y * w0 + x1.y * w1 + x2.y * w2 + x3.y * w3;
    }
    for (; e < end; e++) {
        int2 p0 = __ldg(&ew[e]);
        float2 x0 = bf2f(in[(size_t)p0.x * Hd2 + j]);
        float w0 = __int_as_float(p0.y);
        ax += x0.x * w0;
        ay += x0.y * w0;
    }
    out[(size_t)n * Hd2 + j] = __floats2bfloat162_rn(ax * di, ay * di);
}

// ---------------- merged layer 2 + segment-pool (both graphs) ----------------
__global__ __launch_bounds__(128) void gather2_pool_kernel(
    const __nv_bfloat162* __restrict__ inR, const int* __restrict__ roR,
    const int2* __restrict__ ewR, const float* __restrict__ dR,
    const int* __restrict__ batchR, float* __restrict__ poolR,
    const __nv_bfloat162* __restrict__ inC, const int* __restrict__ roC,
    const int2* __restrict__ ewC, const float* __restrict__ dC,
    const int* __restrict__ batchC, float* __restrict__ poolC)
{
    int n = blockIdx.x;
    const __nv_bfloat162* in; const int* ro; const int2* ew; const float* dv;
    const int* batch; float* pool;
    if (n < NRn) { in = inR; ro = roR; ew = ewR; dv = dR; batch = batchR; pool = poolR; }
    else { n -= NRn; in = inC; ro = roC; ew = ewC; dv = dC; batch = batchC; pool = poolC; }

    int j = threadIdx.x;
    int beg = __ldg(&ro[n]), end = __ldg(&ro[n + 1]);
    float di = __ldg(&dv[n]);
    float2 v = bf2f(in[(size_t)n * Hd2 + j]);
    float ax = fmaxf(v.x, 0.f) * di, ay = fmaxf(v.y, 0.f) * di;
    int e = beg;
    for (; e + 4 <= end; e += 4) {
        int2 p0 = __ldg(&ew[e]);
        int2 p1 = __ldg(&ew[e + 1]);
        int2 p2 = __ldg(&ew[e + 2]);
        int2 p3 = __ldg(&ew[e + 3]);
        float2 x0 = bf2f(in[(size_t)p0.x * Hd2 + j]);
        float2 x1 = bf2f(in[(size_t)p1.x * Hd2 + j]);
        float2 x2 = bf2f(in[(size_t)p2.x * Hd2 + j]);
        float2 x3 = bf2f(in[(size_t)p3.x * Hd2 + j]);
        float w0 = __int_as_float(p0.y), w1 = __int_as_float(p1.y);
        float w2 = __int_as_float(p2.y), w3 = __int_as_float(p3.y);
        ax += fmaxf(x0.x, 0.f) * w0 + fmaxf(x1.x, 0.f) * w1
            + fmaxf(x2.x, 0.f) * w2 + fmaxf(x3.x, 0.f) * w3;
        ay += fmaxf(x0.y, 0.f) * w0 + fmaxf(x1.y, 0.f) * w1
            + fmaxf(x2.y, 0.f) * w2 + fmaxf(x3.y, 0.f) * w3;
    }
    for (; e < end; e++) {
        int2 p0 = __ldg(&ew[e]);
        float2 x0 = bf2f(in[(size_t)p0.x * Hd2 + j]);
        float w0 = __int_as_float(p0.y);
        ax += fmaxf(x0.x, 0.f) * w0;
        ay += fmaxf(x0.y, 0.f) * w0;
    }
    int b = __ldg(&batch[n]);
    float* p = &pool[(size_t)b * Hd + j * 2];
    atomicAdd(p + 0, ax * di);
    atomicAdd(p + 1, ay * di);
}

__device__ __forceinline__ int lower_bound_dev(const int* a, int n, int v) {
    int lo = 0, hi = n;
    while (lo < hi) { int mid = (lo + hi) >> 1; if (a[mid] < v) lo = mid + 1; else hi = mid; }
    return lo;
}

__global__ void pool_partial_kernel(const float* __restrict__ x, const int* __restrict__ seg,
                                    int n, float* __restrict__ acc, int chunks) {
    int b = blockIdx.x;
    int chunk = blockIdx.y;
    int start = lower_bound_dev(seg, n, b);
    int end   = lower_bound_dev(seg, n, b + 1);
    int len = end - start;
    if (len <= 0) return;
    int per = (len + chunks - 1) / chunks;
    int s0 = start + chunk * per;
    int s1 = s0 + per; if (s1 > end) s1 = end;
    if (s0 >= s1) return;
    int j = threadIdx.x;
    float a = 0.0f;
    for (int r = s0; r < s1; r++) a += x[(size_t)r * Hd + j];
    atomicAdd(&acc[b * Hd + j], a);
}

__global__ void pool_div_kernel(const float* __restrict__ acc, const int* __restrict__ seg,
                                int n, float* __restrict__ dst, int ld) {
    int b = blockIdx.x;
    int j = threadIdx.x;
    int cnt = lower_bound_dev(seg, n, b + 1) - lower_bound_dev(seg, n, b);
    float c = fmaxf((float)cnt, 1.0f);
    dst[(size_t)b * ld + j] = acc[b * Hd + j] / c;
}

// ---------------- transpose+bf16 of both fused weights ----------------
__global__ void convtrans2_kernel(const float* __restrict__ W0, __nv_bfloat16* __restrict__ o0,
                                  const float* __restrict__ W1, __nv_bfloat16* __restrict__ o1) {
    int i = blockIdx.x * blockDim.x + threadIdx.x;
    if (i >= Dd * Hd) return;
    const float* W = blockIdx.y ? W1 : W0;
    __nv_bfloat16* o = blockIdx.y ? o1 : o0;
    int k = i / Hd, n = i % Hd;
    o[(size_t)n * Dd + k] = __float2bfloat16(W[i]);
}

// ---------------- tensor-core GEMM: bf16 single-product, double-buffered, dual ----------------
__device__ __forceinline__ void ldsm_x4(uint32_t r[4], const void* p) {
    uint32_t a = (uint32_t)__cvta_generic_to_shared(p);
    asm volatile("ldmatrix.sync.aligned.m8n8.x4.shared.b16 {%0,%1,%2,%3}, [%4];"
                 : "=r"(r[0]), "=r"(r[1]), "=r"(r[2]), "=r"(r[3]) : "r"(a));
}

__device__ __forceinline__ void mma_bf16(float acc[4], uint32_t a0, uint32_t a1,
                                         uint32_t a2, uint32_t a3,
                                         uint32_t b0, uint32_t b1) {
    asm volatile(
        "mma.sync.aligned.m16n8k16.row.col.f32.bf16.bf16.f32 "
        "{%0,%1,%2,%3},{%4,%5,%6,%7},{%8,%9},{%0,%1,%2,%3};"
        : "+f"(acc[0]), "+f"(acc[1]), "+f"(acc[2]), "+f"(acc[3])
        : "r"(a0), "r"(a1), "r"(a2), "r"(a3), "r"(b0), "r"(b1));
}

#define LDS_STRIDE 40
#define NITER (Dd / 32)   // 24

__global__ __launch_bounds__(256) void gemm_bf16_kernel(
    const float* A0, const __nv_bfloat16* Bt0, __nv_bfloat162* C0,
    const float* A1, const __nv_bfloat16* Bt1, __nv_bfloat162* C1, int M)
{
    const float* A = blockIdx.z ? A1 : A0;
    const __nv_bfloat16* Bt = blockIdx.z ? Bt1 : Bt0;
    __nv_bfloat162* C = blockIdx.z ? C1 : C0;

    __shared__ __nv_bfloat16 As[2][128][LDS_STRIDE];
    __shared__ __nv_bfloat16 Bs[2][128][LDS_STRIDE];

    int tid = threadIdx.x;
    int warp = tid >> 5, lane = tid & 31;
    int bRow = blockIdx.y * 128, bCol = blockIdx.x * 128;
    int wm = (warp >> 2) * 64;
    int wn = (warp & 3) * 32;

    float acc[4][4][4];
#pragma unroll
    for (int a = 0; a < 4; a++)
#pragma unroll
        for (int b = 0; b < 4; b++)
#pragma unroll
            for (int c = 0; c < 4; c++) acc[a][b][c] = 0.0f;

    float4 aR[4];
    float4 bR[2];
    const float4 z4 = make_float4(0.f, 0.f, 0.f, 0.f);

#define LOAD_AB(k0)                                                           \
    {                                                                         \
        _Pragma("unroll")                                                     \
        for (int l = 0; l < 4; l++) {                                         \
            int i = tid + l * 256;                                            \
            int r = i >> 3, c4 = (i & 7) * 4;                                 \
            int gr = bRow + r;                                                \
            aR[l] = (gr < M) ? *(const float4*)&A[(size_t)gr * Dd + (k0) + c4]\
                             : z4;                                            \
        }                                                                     \
        _Pragma("unroll")                                                     \
        for (int l = 0; l < 2; l++) {                                         \
            int i = tid + l * 256;                                            \
            int r = i >> 2, c8 = (i & 3) * 8;                                 \
            bR[l] = *(const float4*)&Bt[(size_t)(bCol + r) * Dd + (k0) + c8]; \
        }                                                                     \
    }

#define STORE_AB(st)                                                          \
    {                                                                         \
        _Pragma("unroll")                                                     \
        for (int l = 0; l < 2; l++) {                                         \
            int i = tid + l * 256;                                            \
            int r = i >> 2, c8 = (i & 3) * 8;                                 \
            *(float4*)&Bs[st][r][c8] = bR[l];                                 \
        }                                                                     \
        _Pragma("unroll")                                                     \
        for (int l = 0; l < 4; l++) {                                         \
            int i = tid + l * 256;                                            \
            int r = i >> 3, c4 = (i & 7) * 4;                                 \
            float f[4] = {aR[l].x, aR[l].y, aR[l].z, aR[l].w};                \
            *(__nv_bfloat162*)&As[st][r][c4] =                                \
                __floats2bfloat162_rn(f[0], f[1]);                            \
            *(__nv_bfloat162*)&As[st][r][c4 + 2] =                            \
                __floats2bfloat162_rn(f[2], f[3]);                            \
        }                                                                     \
    }

    LOAD_AB(0);
    STORE_AB(0);
    LOAD_AB(32);
    __syncthreads();

    int mt = lane >> 3, ri = lane & 7;
    for (int it = 0; it < NITER; it++) {
        int cur = it & 1, nxt = cur ^ 1;
        if (it < NITER - 1) {
            STORE_AB(nxt);
            if (it < NITER - 2) LOAD_AB((it + 2) * 32);
        }
#pragma unroll
        for (int ks = 0; ks < 2; ks++) {
            int colOff = ks * 16 + (mt >> 1) * 8;
            uint32_t aH[4][4], bH[2][4];
#pragma unroll
            for (int mi = 0; mi < 4; mi++) {
                int row = wm + mi * 16 + (mt & 1) * 8 + ri;
                ldsm_x4(aH[mi], &As[cur][row][colOff]);
            }
#pragma unroll
            for (int bj = 0; bj < 2; bj++) {
                int row = wn + bj * 16 + (mt & 1) * 8 + ri;
                ldsm_x4(bH[bj], &Bs[cur][row][colOff]);
            }
#pragma unroll
            for (int mi = 0; mi < 4; mi++)
#pragma unroll
                for (int nj = 0; nj < 4; nj++) {
                    int bj = nj >> 1, s = nj & 1;
                    mma_bf16(acc[mi][nj], aH[mi][0], aH[mi][1], aH[mi][2], aH[mi][3],
                             bH[bj][s], bH[bj][s + 2]);
                }
        }
        __syncthreads();
    }
#undef LOAD_AB
#undef STORE_AB

    int g = lane >> 2, t = lane & 3;
#pragma unroll
    for (int mi = 0; mi < 4; mi++)
#pragma unroll
        for (int nj = 0; nj < 4; nj++) {
            int row = bRow + wm + mi * 16 + g;
            int colp = (bCol + wn + nj * 8 + t * 2) >> 1;
            if (row < M)
                C[(size_t)row * Hd2 + colp] = __floats2bfloat162_rn(acc[mi][nj][0], acc[mi][nj][1]);
            if (row + 8 < M)
                C[(size_t)(row + 8) * Hd2 + colp] = __floats2bfloat162_rn(acc[mi][nj][2], acc[mi][nj][3]);
        }
}

// ---------------- small fp32 GEMM (single) ----------------
__global__ __launch_bounds__(256) void sgemm64_kernel(const float* __restrict__ A, int lda,
                                                      const float* __restrict__ Bm,
                                                      const float* __restrict__ bias,
                                                      float* __restrict__ C, int ldc,
                                                      int M, int N, int K, int doRelu) {
    const int BM = 64, BN = 64, BK = 16, TM = 4, TN = 4;
    __shared__ float As[BK][BM];
    __shared__ float Bs[BK][BN];
    const int tid = threadIdx.x;
    const int bRow = blockIdx.y * BM;
    const int bCol = blockIdx.x * BN;
    const int tx = tid % 16;
    const int ty = tid / 16;

    float acc[TM][TN];
#pragma unroll
    for (int i = 0; i < TM; i++)
#pragma unroll
        for (int j = 0; j < TN; j++) acc[i][j] = 0.0f;

    for (int k0 = 0; k0 < K; k0 += BK) {
        {
            int i = tid;
            int r = i >> 2;
            int c4 = (i & 3) << 2;
            int grow = bRow + r;
            float4 v = make_float4(0.f, 0.f, 0.f, 0.f);
            if (grow < M) v = *reinterpret_cast<const float4*>(&A[(size_t)grow * lda + k0 + c4]);
            As[c4 + 0][r] = v.x; As[c4 + 1][r] = v.y; As[c4 + 2][r] = v.z; As[c4 + 3][r] = v.w;
        }
        {
            int i = tid;
            int r = i >> 4;
            int c = (i & 15) << 2;
            float4 v = *reinterpret_cast<const float4*>(&Bm[(size_t)(k0 + r) * N + bCol + c]);
            *reinterpret_cast<float4*>(&Bs[r][c]) = v;
        }
        __syncthreads();

        float ar[TM], br[TN];
#pragma unroll
        for (int kk = 0; kk < BK; kk++) {
#pragma unroll
            for (int i = 0; i < TM; i++) ar[i] = As[kk][ty * TM + i];
#pragma unroll
            for (int j = 0; j < TN; j++) br[j] = Bs[kk][tx * TN + j];
#pragma unroll
            for (int i = 0; i < TM; i++)
#pragma unroll
                for (int j = 0; j < TN; j++) acc[i][j] += ar[i] * br[j];
        }
        __syncthreads();
    }

#pragma unroll
    for (int i = 0; i < TM; i++) {
        int grow = bRow + ty * TM + i;
        if (grow >= M) continue;
#pragma unroll
        for (int j = 0; j < TN; j++) {
            int gcol = bCol + tx * TN + j;
            float v = acc[i][j];
            if (bias) v += bias[gcol];
            if (doRelu) v = fmaxf(v, 0.0f);
            C[(size_t)grow * ldc + gcol] = v;
        }
    }
}

// ---------------- small fp32 GEMM, 3-way z-select ----------------
__global__ __launch_bounds__(256) void sgemm64_3_kernel(
    const float* A0, const float* A1, const float* A2, int lda,
    const float* B0, const float* B1, const float* B2,
    float* C0, float* C1, float* C2, int ldc, int M, int N, int K)
{
    const float* A = (blockIdx.z == 0) ? A0 : (blockIdx.z == 1) ? A1 : A2;
    const float* Bm = (blockIdx.z == 0) ? B0 : (blockIdx.z == 1) ? B1 : B2;
    float* C = (blockIdx.z == 0) ? C0 : (blockIdx.z == 1) ? C1 : C2;

    const int BM = 64, BN = 64, BK = 16, TM = 4, TN = 4;
    __shared__ float As[BK][BM];
    __shared__ float Bs[BK][BN];
    const int tid = threadIdx.x;
    const int bRow = blockIdx.y * BM;
    const int bCol = blockIdx.x * BN;
    const int tx = tid % 16;
    const int ty = tid / 16;

    float acc[TM][TN];
#pragma unroll
    for (int i = 0; i < TM; i++)
#pragma unroll
        for (int j = 0; j < TN; j++) acc[i][j] = 0.0f;

    for (int k0 = 0; k0 < K; k0 += BK) {
        {
            int i = tid;
            int r = i >> 2;
            int c4 = (i & 3) << 2;
            int grow = bRow + r;
            float4 v = make_float4(0.f, 0.f, 0.f, 0.f);
            if (grow < M) v = *reinterpret_cast<const float4*>(&A[(size_t)grow * lda + k0 + c4]);
            As[c4 + 0][r] = v.x; As[c4 + 1][r] = v.y; As[c4 + 2][r] = v.z; As[c4 + 3][r] = v.w;
        }
        {
            int i = tid;
            int r = i >> 4;
            int c = (i & 15) << 2;
            float4 v = *reinterpret_cast<const float4*>(&Bm[(size_t)(k0 + r) * N + bCol + c]);
            *reinterpret_cast<float4*>(&Bs[r][c]) = v;
        }
        __syncthreads();

        float ar[TM], br[TN];
#pragma unroll
        for (int kk = 0; kk < BK; kk++) {
#pragma unroll
            for (int i = 0; i < TM; i++) ar[i] = As[kk][ty * TM + i];
#pragma unroll
            for (int j = 0; j < TN; j++) br[j] = Bs[kk][tx * TN + j];
#pragma unroll
            for (int i = 0; i < TM; i++)
#pragma unroll
                for (int j = 0; j < TN; j++) acc[i][j] += ar[i] * br[j];
        }
        __syncthreads();
    }

#pragma unroll
    for (int i = 0; i < TM; i++) {
        int grow = bRow + ty * TM + i;
        if (grow >= M) continue;
#pragma unroll
        for (int j = 0; j < TN; j++) {
            int gcol = bCol + tx * TN + j;
            C[(size_t)grow * ldc + gcol] = acc[i][j];
        }
    }
}

// ---------------- head ----------------
__global__ void head_kernel(const float* __restrict__ h, const float* __restrict__ W2,
                            const float* __restrict__ b2, const int* __restrict__ label,
                            float* __restrict__ out, int out_size) {
    __shared__ float preds[Bsz][2];
    int tid = threadIdx.x;
    if (tid < Bsz * 2) {
        int r = tid >> 1, c = tid & 1;
        float s = b2[c];
        for (int k = 0; k < Hd; k++) s += h[r * Hd + k] * W2[k * 2 + c];
        preds[r][c] = s;
    }
    __syncthreads();
    if (tid < Bsz * 2 && tid < out_size) out[tid] = preds[tid >> 1][tid & 1];
    if (tid == 0 && out_size >= Bsz * 2 + 1) {
        float loss = 0.0f;
        for (int r = 0; r < Bsz; r++) {
            float a = preds[r][0], b = preds[r][1];
            float m = fmaxf(a, b);
            float lse = m + logf(expf(a - m) + expf(b - m));
            int y = label[r];
            loss += lse - (y ? b : a);
        }
        out[Bsz * 2] = loss / (float)Bsz;
    }
}

// ---------------- launch ----------------
extern "C" void kernel_launch(void* const* d_in, const int* in_sizes, int n_in,
                              void* d_out, int out_size) {
    const float* content  = (const float*)d_in[0];
    const float* video    = (const float*)d_in[1];
    const float* image    = (const float*)d_in[2];
    const float* repost_x = (const float*)d_in[3];
    const float* comment_x= (const float*)d_in[4];
    const float* W_text   = (const float*)d_in[5];
    const float* W_video  = (const float*)d_in[6];
    const float* W_image  = (const float*)d_in[7];
    const float* Wr1      = (const float*)d_in[8];
    const float* Wr2      = (const float*)d_in[9];
    const float* Wc1      = (const float*)d_in[10];
    const float* Wc2      = (const float*)d_in[11];
    const float* W1       = (const float*)d_in[12];
    const float* b1       = (const float*)d_in[13];
    const float* W2       = (const float*)d_in[14];
    const float* b2       = (const float*)d_in[15];
    const int* rei        = (const int*)d_in[16];
    const int* rbatch     = (const int*)d_in[17];
    const int* cei        = (const int*)d_in[18];
    const int* cbatch     = (const int*)d_in[19];
    const int* cgb        = (const int*)d_in[20];
    const int* label      = (const int*)d_in[21];
    float* out            = (float*)d_out;

    __nv_bfloat162 *pXWr, *pP1r, *pXWc, *pP1c;
    float *pDr, *pDc, *pWfr, *pWfc;
    float *pPoolR, *pPoolG, *pGraphs, *pReps, *pHmid;
    __nv_bfloat16 *pWtHiR, *pWtHiC;
    int *pCntR, *pCntC, *pRoR, *pRoC, *pBsum;
    int2 *pEwR, *pEwC;
    cudaGetSymbolAddress((void**)&pXWr, g_XWr);
    cudaGetSymbolAddress((void**)&pP1r, g_P1r);
    cudaGetSymbolAddress((void**)&pXWc, g_XWc);
    cudaGetSymbolAddress((void**)&pP1c, g_P1c);
    cudaGetSymbolAddress((void**)&pDr, g_dinv_r);
    cudaGetSymbolAddress((void**)&pDc, g_dinv_c);
    cudaGetSymbolAddress((void**)&pWfr, g_Wf_r);
    cudaGetSymbolAddress((void**)&pWfc, g_Wf_c);
    cudaGetSymbolAddress((void**)&pWtHiR, g_WtHiR);
    cudaGetSymbolAddress((void**)&pWtHiC, g_WtHiC);
    cudaGetSymbolAddress((void**)&pPoolR, g_pooled_r);
    cudaGetSymbolAddress((void**)&pPoolG, g_pooledG);
    cudaGetSymbolAddress((void**)&pGraphs, g_graphs);
    cudaGetSymbolAddress((void**)&pReps, g_reps);
    cudaGetSymbolAddress((void**)&pHmid, g_hmid);
    cudaGetSymbolAddress((void**)&pCntR, g_cnt_r);
    cudaGetSymbolAddress((void**)&pCntC, g_cnt_c);
    cudaGetSymbolAddress((void**)&pRoR, g_rowoff_r);
    cudaGetSymbolAddress((void**)&pRoC, g_rowoff_c);
    cudaGetSymbolAddress((void**)&pEwR, g_ew_r);
    cudaGetSymbolAddress((void**)&pEwC, g_ew_c);
    cudaGetSymbolAddress((void**)&pBsum, g_bsum2);

    const int* r_src = rei;            const int* r_dst = rei + ERn;
    const int* c_src = cei;            const int* c_dst = cei + ECn;

    const int NB = (NRn + 255) / 256;  // 391 (same for both graphs)

    // ---- zero count arrays (memset nodes, not kernels) ----
    cudaMemsetAsync(pCntR, 0, NRn * sizeof(int));
    cudaMemsetAsync(pCntC, 0, NCn * sizeof(int));

    // kernel 0: count both graphs
    count2_kernel<<<(ERn + 255) / 256, 256>>>(r_dst, c_dst, pCntR, pCntC);
    // kernel 1: fused first-layer weights (both)
    sgemm64_3_kernel<<<dim3(Hd / 64, Dd / 64, 2), 256>>>(
        W_text, W_text, W_text, Hd, Wr1, Wc1, Wc1, pWfr, pWfc, pWfc, Hd, Dd, Hd, Hd);
    // kernel 2: dinv both
    dinv2_kernel<<<NB, 256>>>(pCntR, pCntC, pDr, pDc);
    // kernel 3: transpose+bf16 both
    convtrans2_kernel<<<dim3((Dd * Hd + 255) / 256, 2), 256>>>(pWfr, pWtHiR, pWfc, pWtHiC);
    // kernel 4: scan blocksums both
    scan_blocksum2_kernel<<<dim3(NB, 2), 256>>>(pCntR, pCntC, pBsum, NRn);
    // kernel 5: dual tensor-core GEMM  (ncu capture target)
    gemm_bf16_kernel<<<dim3(2, (NRn + 127) / 128, 2), 256>>>(
        repost_x, pWtHiR, pXWr, comment_x, pWtHiC, pXWc, NRn);
    // kernel 6-7: finish scans
    scan_bsum2_kernel<<<dim3(1, 2), 512>>>(pBsum, pRoR, pRoC, NB, NRn);
    scan_final2_kernel<<<dim3(NB, 2), 256>>>(pCntR, pCntC, pBsum, pRoR, pRoC, NRn);
    // zero cursors, then scatter with (src, dinv_src) payload
    cudaMemsetAsync(pCntR, 0, NRn * sizeof(int));
    cudaMemsetAsync(pCntC, 0, NCn * sizeof(int));
    scatter2_kernel<<<dim3((ERn + 255) / 256, 2), 256>>>(
        r_src, r_dst, pRoR, pCntR, pDr, pEwR,
        c_src, c_dst, pRoC, pCntC, pDc, pEwC);

    // ---- layer-1 gather (both graphs, one launch) ----
    gather1_kernel<<<NRn + NCn, 128>>>(pXWr, pP1r, pRoR, pEwR, pDr,
                                       pXWc, pP1c, pRoC, pEwC, pDc);

    // ---- layer-2 + pooling (both graphs, one launch) ----
    cudaMemsetAsync(pPoolR, 0, (size_t)Bsz * Hd * sizeof(float));
    cudaMemsetAsync(pPoolG, 0, (size_t)Gn * Hd * sizeof(float));
    gather2_pool_kernel<<<NRn + NCn, 128>>>(pP1r, pRoR, pEwR, pDr, rbatch, pPoolR,
                                            pP1c, pRoC, pEwC, pDc, cbatch, pPoolG);
    pool_div_kernel<<<Bsz, Hd>>>(pPoolR, rbatch, NRn, pPoolR, Hd);
    pool_div_kernel<<<Gn, Hd>>>(pPoolG, cbatch, NCn, pPoolG, Hd);

    // graphs_reps = pooledG @ Wc2
    sgemm64_kernel<<<dim3(Hd / 64, Gn / 64), 256>>>(pPoolG, Hd, Wc2, nullptr, pGraphs, Hd, Gn, Hd, Hd, 0);
    cudaMemsetAsync(pHmid, 0, (size_t)Bsz * Hd * sizeof(float));
    pool_partial_kernel<<<dim3(Bsz, 2), Hd>>>(pGraphs, cgb, Gn, pHmid, 2);
    pool_div_kernel<<<Bsz, Hd>>>(pHmid, cgb, Gn, pReps + 2 * Hd, 5 * Hd);

    // ---- reps: content/video/image in one launch, repost in another ----
    sgemm64_3_kernel<<<dim3(Hd / 64, 1, 3), 256>>>(
        content, video, image, Dd, W_text, W_video, W_image,
        pReps + 0 * Hd, pReps + 3 * Hd, pReps + 4 * Hd, 5 * Hd, Bsz, Hd, Dd);
    sgemm64_kernel<<<dim3(Hd / 64, 1), 256>>>(pPoolR, Hd, Wr2, nullptr, pReps + 1 * Hd, 5 * Hd, Bsz, Hd, Hd, 0);

    // ---- MLP head ----
    sgemm64_kernel<<<dim3(Hd / 64, 1), 256>>>(pReps, 5 * Hd, W1, b1, pHmid, Hd, Bsz, Hd, 5 * Hd, 1);
    head_kernel<<<1, 128>>>(pHmid, W2, b2, label, out, out_size);
}